// round 1
// baseline (speedup 1.0000x reference)
#include <cuda_runtime.h>
#include <cuda_bf16.h>
#include <math.h>

// ---------------- problem constants ----------------
#define B_  4
#define L_  2048
#define C_  384
#define H_  12
#define N_  64
#define DI_ 768
#define DH_ 64
#define HID_ 1536
#define PROJ_ 1676          // 2*DI + 2*N + H
#define M_  (B_*L_)         // 8192
#define EPS_ 1e-5f

// ---------------- scratch (no allocations allowed) ----------------
__device__ float g_xln  [M_*C_];
__device__ float g_projf[M_*PROJ_];
__device__ float g_projb[M_*PROJ_];
__device__ float g_gatedf[M_*DI_];
__device__ float g_gatedb[M_*DI_];
__device__ float g_outf [M_*C_];
__device__ float g_outb [M_*C_];
__device__ float g_x2   [M_*C_];
__device__ float g_h2   [M_*C_];
__device__ float g_hid  [M_*HID_];

// ---------------- block reduction (128 threads) ----------------
__device__ __forceinline__ float blockSum128(float v) {
    __shared__ float sh[4];
    int lane = threadIdx.x & 31, w = threadIdx.x >> 5;
    #pragma unroll
    for (int o = 16; o; o >>= 1) v += __shfl_xor_sync(0xffffffffu, v, o);
    if (lane == 0) sh[w] = v;
    __syncthreads();
    float r = sh[0] + sh[1] + sh[2] + sh[3];
    __syncthreads();
    return r;
}

// ---------------- LayerNorm 1 ----------------
__global__ void ln1_kernel(const float* __restrict__ x,
                           const float* __restrict__ g,
                           const float* __restrict__ be,
                           float* __restrict__ o) {
    size_t row = blockIdx.x;
    const float* xr = x + row * C_;
    int t = threadIdx.x;
    float v0 = xr[t], v1 = xr[t + 128], v2 = xr[t + 256];
    float mu = blockSum128(v0 + v1 + v2) * (1.f / C_);
    float d0 = v0 - mu, d1 = v1 - mu, d2 = v2 - mu;
    float var = blockSum128(d0*d0 + d1*d1 + d2*d2) * (1.f / C_);
    float inv = rsqrtf(var + EPS_);
    float* orow = o + row * C_;
    orow[t]       = d0 * inv * g[t]       + be[t];
    orow[t + 128] = d1 * inv * g[t + 128] + be[t + 128];
    orow[t + 256] = d2 * inv * g[t + 256] + be[t + 256];
}

// ---------------- residual sum + LayerNorm 2 (fused) ----------------
__global__ void ln2_kernel(const float* __restrict__ of,
                           const float* __restrict__ ob,
                           const float* __restrict__ pts,
                           const float* __restrict__ g,
                           const float* __restrict__ be,
                           float* __restrict__ x2,
                           float* __restrict__ h2) {
    size_t row = blockIdx.x;
    size_t base = row * C_;
    int t = threadIdx.x;
    float v0 = of[base+t]     + ob[base+t]     + pts[base+t];
    float v1 = of[base+t+128] + ob[base+t+128] + pts[base+t+128];
    float v2 = of[base+t+256] + ob[base+t+256] + pts[base+t+256];
    x2[base+t] = v0; x2[base+t+128] = v1; x2[base+t+256] = v2;
    float mu = blockSum128(v0 + v1 + v2) * (1.f / C_);
    float d0 = v0 - mu, d1 = v1 - mu, d2 = v2 - mu;
    float var = blockSum128(d0*d0 + d1*d1 + d2*d2) * (1.f / C_);
    float inv = rsqrtf(var + EPS_);
    h2[base+t]       = d0 * inv * g[t]       + be[t];
    h2[base+t+128]   = d1 * inv * g[t+128]   + be[t+128];
    h2[base+t+256]   = d2 * inv * g[t+256]   + be[t+256];
}

// ---------------- tiled fp32 GEMM ----------------
// C[M,N] = A[M,K] @ B + bias (+ epilogue)
// BT=false: B is (K,N) row-major.  BT=true: B is (N,K) row-major (i.e. A@B^T).
// EPI: 0 = +bias; 1 = +bias, *bn_scale, +bn_bias, relu; 2 = +bias + residual(e1)
#define BM 64
#define BN 64
#define BK 16

template<bool BT, int EPI>
__global__ __launch_bounds__(256)
void gemm_kernel(const float* __restrict__ A, const float* __restrict__ Bm,
                 const float* __restrict__ bias, float* __restrict__ C,
                 int M, int N, int K,
                 const float* __restrict__ e1, const float* __restrict__ e2) {
    __shared__ float As[BK][BM + 4];
    __shared__ float Bs[BK][BN + 4];
    int tid = threadIdx.x;
    int tx = tid & 15, ty = tid >> 4;
    int gm0 = blockIdx.y * BM;
    int gn0 = blockIdx.x * BN;

    float acc[4][4] = {};

    int ar  = tid >> 2;         // 0..63 row within tile
    int ac4 = (tid & 3) << 2;   // k offset: 0,4,8,12
    int bk0 = tid >> 6;         // 0..3 (NN path)
    int bn  = tid & 63;

    int nkt = K / BK;
    for (int kt = 0; kt < nkt; ++kt) {
        int gk = kt * BK;
        float4 av = *(const float4*)(A + (size_t)(gm0 + ar) * K + gk + ac4);
        float4 bv;
        float bsc[4];
        if (BT) {
            bv = *(const float4*)(Bm + (size_t)(gn0 + ar) * K + gk + ac4);
        } else {
            #pragma unroll
            for (int i = 0; i < 4; i++) {
                int kk = bk0 + i * 4;
                int n = gn0 + bn;
                bsc[i] = (n < N) ? Bm[(size_t)(gk + kk) * N + n] : 0.f;
            }
        }
        __syncthreads();
        As[ac4 + 0][ar] = av.x; As[ac4 + 1][ar] = av.y;
        As[ac4 + 2][ar] = av.z; As[ac4 + 3][ar] = av.w;
        if (BT) {
            Bs[ac4 + 0][ar] = bv.x; Bs[ac4 + 1][ar] = bv.y;
            Bs[ac4 + 2][ar] = bv.z; Bs[ac4 + 3][ar] = bv.w;
        } else {
            #pragma unroll
            for (int i = 0; i < 4; i++) Bs[bk0 + i * 4][bn] = bsc[i];
        }
        __syncthreads();
        #pragma unroll
        for (int kk = 0; kk < BK; ++kk) {
            float4 a4 = *(const float4*)&As[kk][ty * 4];
            float4 b4 = *(const float4*)&Bs[kk][tx * 4];
            float a[4] = {a4.x, a4.y, a4.z, a4.w};
            float b[4] = {b4.x, b4.y, b4.z, b4.w};
            #pragma unroll
            for (int i = 0; i < 4; i++)
                #pragma unroll
                for (int j = 0; j < 4; j++)
                    acc[i][j] = fmaf(a[i], b[j], acc[i][j]);
        }
    }

    const float bnrs = rsqrtf(1.f + EPS_);
    #pragma unroll
    for (int i = 0; i < 4; i++) {
        int m = gm0 + ty * 4 + i;
        #pragma unroll
        for (int j = 0; j < 4; j++) {
            int n = gn0 + tx * 4 + j;
            if (n < N) {
                float v = acc[i][j] + bias[n];
                if (EPI == 1) {
                    v = v * (e1[n] * bnrs) + e2[n];
                    v = fmaxf(v, 0.f);
                } else if (EPI == 2) {
                    v += e1[(size_t)m * N + n];
                }
                C[(size_t)m * N + n] = v;
            }
        }
    }
}

// ---------------- selective scan (both directions), fused D*x + silu gate ----
// grid = 2*B*H = 96 blocks, 256 threads.
// thread t: d = t>>2 (0..63), q = t&3 -> owns n in [q*16, q*16+16)
__global__ __launch_bounds__(256)
void scan_kernel(const float* __restrict__ projf, const float* __restrict__ projb,
                 const float* __restrict__ dtbf, const float* __restrict__ Alogf,
                 const float* __restrict__ Df,
                 const float* __restrict__ dtbb, const float* __restrict__ Alogb,
                 const float* __restrict__ Db,
                 float* __restrict__ gatedf, float* __restrict__ gatedb) {
    int bx = blockIdx.x;
    int dir = bx / (B_ * H_);
    int rem = bx % (B_ * H_);
    int b = rem / H_;
    int h = rem % H_;

    const float* proj  = dir ? projb  : projf;
    const float* dtb   = dir ? dtbb   : dtbf;
    const float* Alog  = dir ? Alogb  : Alogf;
    const float* Dv    = dir ? Db     : Df;
    float*       gated = dir ? gatedb : gatedf;

    int t = threadIdx.x;
    int d = t >> 2, q = t & 3, nb = q << 4;

    __shared__ float xsh[64], zsh[64], Bsh[64], Csh[64];
    __shared__ float dtsh;

    float A    = -expf(Alog[h]);
    float dtbh = dtb[h];
    float Dd   = Dv[h * 64 + d];

    int grp = t >> 6;      // 0:x 1:z 2:B 3:C
    int off = t & 63;
    float* psh = (grp == 0) ? xsh : (grp == 1) ? zsh : (grp == 2) ? Bsh : Csh;
    int base = (grp == 0) ? (DI_ + h * 64) :
               (grp == 1) ? (h * 64) :
               (grp == 2) ? (2 * DI_) : (2 * DI_ + N_);

    float hreg[16];
    #pragma unroll
    for (int i = 0; i < 16; i++) hreg[i] = 0.f;

    // prefetch step 0
    int l0 = dir ? (L_ - 1) : 0;
    size_t ro = ((size_t)b * L_ + l0) * PROJ_;
    float pf = proj[ro + base + off];
    float pfd = 0.f;
    if (t == 0) pfd = proj[ro + 2 * DI_ + 2 * N_ + h];

    for (int s = 0; s < L_; ++s) {
        int lcur = dir ? (L_ - 1 - s) : s;
        __syncthreads();            // previous step done reading shared
        psh[off] = pf;
        if (t == 0) dtsh = pfd;
        __syncthreads();
        if (s + 1 < L_) {           // prefetch next step (latency hidden)
            int ln = dir ? (L_ - 2 - s) : (s + 1);
            size_t rn = ((size_t)b * L_ + ln) * PROJ_;
            pf = proj[rn + base + off];
            if (t == 0) pfd = proj[rn + 2 * DI_ + 2 * N_ + h];
        }
        float dtv = dtsh + dtbh;
        dtv = (dtv > 20.f) ? dtv : log1pf(expf(dtv));
        float a = expf(dtv * A);
        float xd = xsh[d];
        float coef = dtv * xd;
        float acc = 0.f;
        #pragma unroll
        for (int i = 0; i < 16; i++) {
            float hv = fmaf(a, hreg[i], coef * Bsh[nb + i]);
            hreg[i] = hv;
            acc = fmaf(hv, Csh[nb + i], acc);
        }
        acc += __shfl_xor_sync(0xffffffffu, acc, 1);
        acc += __shfl_xor_sync(0xffffffffu, acc, 2);
        if (q == 0) {
            float y = acc + Dd * xd;
            float z = zsh[d];
            float sig = 1.f / (1.f + expf(-z));
            gated[((size_t)b * L_ + lcur) * DI_ + h * 64 + d] = y * (z * sig);
        }
    }
}

// ---------------- host launch ----------------
static float* sym(const void* s) {
    void* p = nullptr;
    cudaGetSymbolAddress(&p, s);
    return (float*)p;
}

extern "C" void kernel_launch(void* const* d_in, const int* in_sizes, int n_in,
                              void* d_out, int out_size) {
    const float* points = (const float*)d_in[0];
    const float* g1  = (const float*)d_in[1];
    const float* be1 = (const float*)d_in[2];
    const float* g2  = (const float*)d_in[3];
    const float* be2 = (const float*)d_in[4];
    const float* Winf  = (const float*)d_in[5];
    const float* binf  = (const float*)d_in[6];
    const float* dtbf  = (const float*)d_in[7];
    const float* Alogf = (const float*)d_in[8];
    const float* Df    = (const float*)d_in[9];
    const float* Woutf = (const float*)d_in[10];
    const float* boutf = (const float*)d_in[11];
    const float* Winb  = (const float*)d_in[12];
    const float* binb  = (const float*)d_in[13];
    const float* dtbb  = (const float*)d_in[14];
    const float* Alogb = (const float*)d_in[15];
    const float* Db    = (const float*)d_in[16];
    const float* Woutb = (const float*)d_in[17];
    const float* boutb = (const float*)d_in[18];
    const float* W1  = (const float*)d_in[19];
    const float* b1m = (const float*)d_in[20];
    const float* bng = (const float*)d_in[21];
    const float* bnb = (const float*)d_in[22];
    const float* W2  = (const float*)d_in[23];
    const float* b2m = (const float*)d_in[24];
    float* out = (float*)d_out;

    float* xln    = sym(g_xln);
    float* projf  = sym(g_projf);
    float* projb  = sym(g_projb);
    float* gatedf = sym(g_gatedf);
    float* gatedb = sym(g_gatedb);
    float* outf   = sym(g_outf);
    float* outb   = sym(g_outb);
    float* x2     = sym(g_x2);
    float* h2     = sym(g_h2);
    float* hid    = sym(g_hid);

    // 1. LN1
    ln1_kernel<<<M_, 128>>>(points, g1, be1, xln);

    // 2/3. input projections (N=1676 not multiple of 64 -> guarded NN path)
    dim3 gproj((PROJ_ + BN - 1) / BN, M_ / BM);
    gemm_kernel<false, 0><<<gproj, 256>>>(xln, Winf, binf, projf, M_, PROJ_, C_, nullptr, nullptr);
    gemm_kernel<false, 0><<<gproj, 256>>>(xln, Winb, binb, projb, M_, PROJ_, C_, nullptr, nullptr);

    // 4. bidirectional scan + gating
    scan_kernel<<<2 * B_ * H_, 256>>>(projf, projb, dtbf, Alogf, Df,
                                      dtbb, Alogb, Db, gatedf, gatedb);

    // 5/6. output projections
    dim3 gwout(C_ / BN, M_ / BM);
    gemm_kernel<false, 0><<<gwout, 256>>>(gatedf, Woutf, boutf, outf, M_, C_, DI_, nullptr, nullptr);
    gemm_kernel<false, 0><<<gwout, 256>>>(gatedb, Woutb, boutb, outb, M_, C_, DI_, nullptr, nullptr);

    // 7. residual sum + LN2
    ln2_kernel<<<M_, 128>>>(outf, outb, points, g2, be2, x2, h2);

    // 8. MLP up: h2 @ W1^T + b1m, *bn_scale, +bn_bias, relu
    dim3 gmlp1(HID_ / BN, M_ / BM);
    gemm_kernel<true, 1><<<gmlp1, 256>>>(h2, W1, b1m, hid, M_, HID_, C_, bng, bnb);

    // 9. MLP down: hid @ W2^T + b2m + x2 -> d_out
    dim3 gmlp2(C_ / BN, M_ / BM);
    gemm_kernel<true, 2><<<gmlp2, 256>>>(hid, W2, b2m, out, M_, C_, HID_, x2, nullptr);
}

// round 2
// speedup vs baseline: 1.2354x; 1.2354x over previous
#include <cuda_runtime.h>
#include <cuda_bf16.h>
#include <math.h>

// ---------------- problem constants ----------------
#define B_   4
#define L_   2048
#define C_   384
#define H_   12
#define N_   64
#define DI_  768
#define DI2_ 1536
#define HID_ 1536
#define PROJ_ 1676          // 2*DI + 2*N + H
#define M_   (B_*L_)        // 8192
#define EPS_ 1e-5f

// ---------------- scratch (no allocations allowed) ----------------
__device__ float g_xln  [M_*C_];
__device__ float g_projf[M_*PROJ_];
__device__ float g_projb[M_*PROJ_];
__device__ float g_gated[M_*DI2_];     // [fwd(768) | bwd(768)] per row
__device__ float g_x2   [M_*C_];
__device__ float g_h2   [M_*C_];
__device__ float g_hid  [M_*HID_];
__device__ float g_wcat [DI2_*C_];     // [Woutf ; Woutb] stacked on K
__device__ float g_bcat [C_];

// ---------------- block reduction (128 threads) ----------------
__device__ __forceinline__ float blockSum128(float v) {
    __shared__ float sh[4];
    int lane = threadIdx.x & 31, w = threadIdx.x >> 5;
    #pragma unroll
    for (int o = 16; o; o >>= 1) v += __shfl_xor_sync(0xffffffffu, v, o);
    if (lane == 0) sh[w] = v;
    __syncthreads();
    float r = sh[0] + sh[1] + sh[2] + sh[3];
    __syncthreads();
    return r;
}

// ---------------- LayerNorm (row of 384) ----------------
__global__ void ln_kernel(const float* __restrict__ x,
                          const float* __restrict__ g,
                          const float* __restrict__ be,
                          float* __restrict__ o) {
    size_t row = blockIdx.x;
    const float* xr = x + row * C_;
    int t = threadIdx.x;
    float v0 = xr[t], v1 = xr[t + 128], v2 = xr[t + 256];
    float mu = blockSum128(v0 + v1 + v2) * (1.f / C_);
    float d0 = v0 - mu, d1 = v1 - mu, d2 = v2 - mu;
    float var = blockSum128(d0*d0 + d1*d1 + d2*d2) * (1.f / C_);
    float inv = rsqrtf(var + EPS_);
    float* orow = o + row * C_;
    orow[t]       = d0 * inv * g[t]       + be[t];
    orow[t + 128] = d1 * inv * g[t + 128] + be[t + 128];
    orow[t + 256] = d2 * inv * g[t + 256] + be[t + 256];
}

// ---------------- weight concat for fused output projection ----------------
__global__ void prep_wcat(const float* __restrict__ Wf, const float* __restrict__ Wb,
                          const float* __restrict__ bf, const float* __restrict__ bb,
                          float* __restrict__ Wcat, float* __restrict__ bcat) {
    int i = blockIdx.x * 256 + threadIdx.x;
    if (i < DI_ * C_) {
        Wcat[i] = Wf[i];
        Wcat[DI_ * C_ + i] = Wb[i];
    }
    if (i < C_) bcat[i] = bf[i] + bb[i];
}

// ---------------- tiled fp32 GEMM: 128x128x16, 8x8/thread, double buffered ----
// C[M,N] = A[M,K] @ B + bias (+ epilogue)
// BT=false: B is (K,N) row-major.  BT=true: B is (N,K) row-major (A@B^T).
// EPI: 0 = +bias; 1 = +bias,*bn_scale,+bn_bias,relu; 2 = +bias + residual(e1)
#define BM 128
#define BN 128
#define BK 16

template<bool BT, int EPI>
__global__ __launch_bounds__(256, 2)
void gemm_kernel(const float* __restrict__ A, const float* __restrict__ Bm,
                 const float* __restrict__ bias, float* __restrict__ C,
                 int M, int N, int K,
                 const float* __restrict__ e1, const float* __restrict__ e2) {
    __shared__ float As[2][BK][BM + 4];
    __shared__ float Bs[2][BK][BN + 4];
    int tid = threadIdx.x;
    int tx = tid & 15, ty = tid >> 4;
    int gm0 = blockIdx.y * BM, gn0 = blockIdx.x * BN;

    // A / BT-B load indices (row within tile, k offset)
    int ar = tid >> 2;              // 0..63
    int ac = (tid & 3) << 2;        // 0,4,8,12
    // NN-B load indices
    int bk = tid >> 4;              // 0..15
    int bn = (tid & 15) << 2;       // 0..60

    float4 a0, a1, b0, b1;
    const float4 z4 = {0.f, 0.f, 0.f, 0.f};

    // ---- prologue: load k-tile 0 ----
    {
        const float* Ap = A + (size_t)(gm0 + ar) * K + ac;
        a0 = *(const float4*)(Ap);
        a1 = *(const float4*)(Ap + (size_t)64 * K);
        if (BT) {
            const float* Bp = Bm + (size_t)(gn0 + ar) * K + ac;
            b0 = *(const float4*)(Bp);
            b1 = *(const float4*)(Bp + (size_t)64 * K);
        } else {
            int n0 = gn0 + bn;
            const float* Bp = Bm + (size_t)bk * N;
            b0 = (n0 < N) ? *(const float4*)(Bp + n0) : z4;
            b1 = (n0 + 64 < N) ? *(const float4*)(Bp + n0 + 64) : z4;
        }
    }
    // store to buffer 0
    As[0][ac+0][ar] = a0.x; As[0][ac+1][ar] = a0.y; As[0][ac+2][ar] = a0.z; As[0][ac+3][ar] = a0.w;
    As[0][ac+0][ar+64] = a1.x; As[0][ac+1][ar+64] = a1.y; As[0][ac+2][ar+64] = a1.z; As[0][ac+3][ar+64] = a1.w;
    if (BT) {
        Bs[0][ac+0][ar] = b0.x; Bs[0][ac+1][ar] = b0.y; Bs[0][ac+2][ar] = b0.z; Bs[0][ac+3][ar] = b0.w;
        Bs[0][ac+0][ar+64] = b1.x; Bs[0][ac+1][ar+64] = b1.y; Bs[0][ac+2][ar+64] = b1.z; Bs[0][ac+3][ar+64] = b1.w;
    } else {
        *(float4*)&Bs[0][bk][bn] = b0;
        *(float4*)&Bs[0][bk][bn + 64] = b1;
    }
    __syncthreads();

    float acc[8][8];
    #pragma unroll
    for (int i = 0; i < 8; i++)
        #pragma unroll
        for (int j = 0; j < 8; j++) acc[i][j] = 0.f;

    int nkt = K / BK;
    int buf = 0;
    for (int kt = 0; kt < nkt; ++kt) {
        // prefetch next tile into registers
        if (kt + 1 < nkt) {
            int gk = (kt + 1) * BK;
            const float* Ap = A + (size_t)(gm0 + ar) * K + gk + ac;
            a0 = *(const float4*)(Ap);
            a1 = *(const float4*)(Ap + (size_t)64 * K);
            if (BT) {
                const float* Bp = Bm + (size_t)(gn0 + ar) * K + gk + ac;
                b0 = *(const float4*)(Bp);
                b1 = *(const float4*)(Bp + (size_t)64 * K);
            } else {
                int n0 = gn0 + bn;
                const float* Bp = Bm + (size_t)(gk + bk) * N;
                b0 = (n0 < N) ? *(const float4*)(Bp + n0) : z4;
                b1 = (n0 + 64 < N) ? *(const float4*)(Bp + n0 + 64) : z4;
            }
        }
        // compute from current buffer
        #pragma unroll
        for (int kk = 0; kk < BK; ++kk) {
            float4 x0 = *(const float4*)&As[buf][kk][ty * 4];
            float4 x1 = *(const float4*)&As[buf][kk][ty * 4 + 64];
            float4 y0 = *(const float4*)&Bs[buf][kk][tx * 4];
            float4 y1 = *(const float4*)&Bs[buf][kk][tx * 4 + 64];
            float av[8] = {x0.x, x0.y, x0.z, x0.w, x1.x, x1.y, x1.z, x1.w};
            float bv[8] = {y0.x, y0.y, y0.z, y0.w, y1.x, y1.y, y1.z, y1.w};
            #pragma unroll
            for (int i = 0; i < 8; i++)
                #pragma unroll
                for (int j = 0; j < 8; j++)
                    acc[i][j] = fmaf(av[i], bv[j], acc[i][j]);
        }
        // stage next tile into other buffer
        if (kt + 1 < nkt) {
            int nb2 = buf ^ 1;
            As[nb2][ac+0][ar] = a0.x; As[nb2][ac+1][ar] = a0.y; As[nb2][ac+2][ar] = a0.z; As[nb2][ac+3][ar] = a0.w;
            As[nb2][ac+0][ar+64] = a1.x; As[nb2][ac+1][ar+64] = a1.y; As[nb2][ac+2][ar+64] = a1.z; As[nb2][ac+3][ar+64] = a1.w;
            if (BT) {
                Bs[nb2][ac+0][ar] = b0.x; Bs[nb2][ac+1][ar] = b0.y; Bs[nb2][ac+2][ar] = b0.z; Bs[nb2][ac+3][ar] = b0.w;
                Bs[nb2][ac+0][ar+64] = b1.x; Bs[nb2][ac+1][ar+64] = b1.y; Bs[nb2][ac+2][ar+64] = b1.z; Bs[nb2][ac+3][ar+64] = b1.w;
            } else {
                *(float4*)&Bs[nb2][bk][bn] = b0;
                *(float4*)&Bs[nb2][bk][bn + 64] = b1;
            }
            __syncthreads();
            buf ^= 1;
        }
    }

    // ---- epilogue ----
    const float bnrs = rsqrtf(1.f + EPS_);
    #pragma unroll
    for (int ih = 0; ih < 2; ih++) {
        #pragma unroll
        for (int i = 0; i < 4; i++) {
            int m = gm0 + ty * 4 + i + ih * 64;
            #pragma unroll
            for (int jh = 0; jh < 2; jh++) {
                int n = gn0 + tx * 4 + jh * 64;
                if (n < N) {
                    float* accr = &acc[ih * 4 + i][jh * 4];
                    float4 v;
                    float4 bs4 = *(const float4*)(bias + n);
                    v.x = accr[0] + bs4.x; v.y = accr[1] + bs4.y;
                    v.z = accr[2] + bs4.z; v.w = accr[3] + bs4.w;
                    if (EPI == 1) {
                        float4 s4 = *(const float4*)(e1 + n);
                        float4 t4 = *(const float4*)(e2 + n);
                        v.x = fmaxf(v.x * (s4.x * bnrs) + t4.x, 0.f);
                        v.y = fmaxf(v.y * (s4.y * bnrs) + t4.y, 0.f);
                        v.z = fmaxf(v.z * (s4.z * bnrs) + t4.z, 0.f);
                        v.w = fmaxf(v.w * (s4.w * bnrs) + t4.w, 0.f);
                    } else if (EPI == 2) {
                        float4 r4 = *(const float4*)(e1 + (size_t)m * N + n);
                        v.x += r4.x; v.y += r4.y; v.z += r4.z; v.w += r4.w;
                    }
                    *(float4*)(C + (size_t)m * N + n) = v;
                }
            }
        }
    }
}

// ---------------- selective scan (both directions), fused D*x + silu gate ----
// grid = 2*B*H = 96 blocks, 256 threads.
// thread t: d = t>>2 (0..63), q = t&3 -> owns n in [q*16, q*16+16)
// writes into combined gated buffer: row stride DI2_, fwd cols [0,768), bwd [768,1536)
__global__ __launch_bounds__(256)
void scan_kernel(const float* __restrict__ projf, const float* __restrict__ projb,
                 const float* __restrict__ dtbf, const float* __restrict__ Alogf,
                 const float* __restrict__ Df,
                 const float* __restrict__ dtbb, const float* __restrict__ Alogb,
                 const float* __restrict__ Db,
                 float* __restrict__ gated) {
    int bx = blockIdx.x;
    int dir = bx / (B_ * H_);
    int rem = bx % (B_ * H_);
    int b = rem / H_;
    int h = rem % H_;

    const float* proj = dir ? projb  : projf;
    const float* dtb  = dir ? dtbb   : dtbf;
    const float* Alog = dir ? Alogb  : Alogf;
    const float* Dv   = dir ? Db     : Df;

    int t = threadIdx.x;
    int d = t >> 2, q = t & 3, nb = q << 4;

    __shared__ float sm[2][256];   // [x(64) | z(64) | B(64) | C(64)]

    float A    = -expf(Alog[h]);
    float dtbh = dtb[h];
    float Dd   = Dv[h * 64 + d];

    int grp = t >> 6;      // 0:x 1:z 2:B 3:C
    int off = t & 63;
    int slot = grp * 64 + off;
    int base = (grp == 0) ? (DI_ + h * 64) :
               (grp == 1) ? (h * 64) :
               (grp == 2) ? (2 * DI_) : (2 * DI_ + N_);
    int dtcol = 2 * DI_ + 2 * N_ + h;

    float hreg[16];
    #pragma unroll
    for (int i = 0; i < 16; i++) hreg[i] = 0.f;

    long pstride = dir ? -(long)PROJ_ : (long)PROJ_;
    long gstride = dir ? -(long)DI2_  : (long)DI2_;
    const float* p0 = proj + ((size_t)b * L_ + (dir ? L_ - 1 : 0)) * PROJ_;
    float* go = gated + ((size_t)b * L_ + (dir ? L_ - 1 : 0)) * DI2_
                      + (dir ? DI_ : 0) + h * 64 + d;

    // prefetch pipeline: rows s=0..3
    float v0 = p0[base + off];
    float dcur = p0[dtcol];
    const float* p = p0 + pstride;
    float v1 = p[base + off];
    float d1r = p[dtcol];
    p += pstride;
    float v2 = p[base + off];
    float d2r = p[dtcol];
    const float* pnext = p + pstride;   // row 3

    sm[0][slot] = v0;
    __syncthreads();
    int buf = 0;

    for (int s = 0; s < L_; ++s) {
        float vload = 0.f, dload = 0.f;
        if (s + 3 < L_) {
            vload = pnext[base + off];
            dload = pnext[dtcol];
            pnext += pstride;
        }
        float dtv = dcur + dtbh;
        dtv = (dtv > 20.f) ? dtv : log1pf(__expf(dtv));
        float a = __expf(dtv * A);

        const float* S = sm[buf];
        float xd = S[d];
        float coef = dtv * xd;
        const float4* Bv = (const float4*)(S + 128 + nb);
        const float4* Cv = (const float4*)(S + 192 + nb);
        float acc0 = 0.f, acc1 = 0.f;
        #pragma unroll
        for (int i4 = 0; i4 < 4; i4++) {
            float4 bb = Bv[i4];
            float4 cc = Cv[i4];
            float h0 = fmaf(a, hreg[i4*4+0], coef * bb.x);
            float h1 = fmaf(a, hreg[i4*4+1], coef * bb.y);
            float h2 = fmaf(a, hreg[i4*4+2], coef * bb.z);
            float h3 = fmaf(a, hreg[i4*4+3], coef * bb.w);
            hreg[i4*4+0] = h0; hreg[i4*4+1] = h1;
            hreg[i4*4+2] = h2; hreg[i4*4+3] = h3;
            acc0 = fmaf(h0, cc.x, acc0);
            acc1 = fmaf(h1, cc.y, acc1);
            acc0 = fmaf(h2, cc.z, acc0);
            acc1 = fmaf(h3, cc.w, acc1);
        }
        float acc = acc0 + acc1;
        acc += __shfl_xor_sync(0xffffffffu, acc, 1);
        acc += __shfl_xor_sync(0xffffffffu, acc, 2);
        if (q == 0) {
            float y = acc + Dd * xd;
            float z = S[64 + d];
            float sig = 1.f / (1.f + __expf(-z));
            *go = y * (z * sig);
        }
        go += gstride;

        if (s + 1 < L_) {
            sm[buf ^ 1][slot] = v1;
            __syncthreads();
            buf ^= 1;
        }
        // shift pipeline
        v1 = v2;  v2 = vload;
        dcur = d1r; d1r = d2r; d2r = dload;
    }
}

// ---------------- host launch ----------------
static float* sym(const void* s) {
    void* p = nullptr;
    cudaGetSymbolAddress(&p, s);
    return (float*)p;
}

extern "C" void kernel_launch(void* const* d_in, const int* in_sizes, int n_in,
                              void* d_out, int out_size) {
    const float* points = (const float*)d_in[0];
    const float* g1  = (const float*)d_in[1];
    const float* be1 = (const float*)d_in[2];
    const float* g2  = (const float*)d_in[3];
    const float* be2 = (const float*)d_in[4];
    const float* Winf  = (const float*)d_in[5];
    const float* binf  = (const float*)d_in[6];
    const float* dtbf  = (const float*)d_in[7];
    const float* Alogf = (const float*)d_in[8];
    const float* Df    = (const float*)d_in[9];
    const float* Woutf = (const float*)d_in[10];
    const float* boutf = (const float*)d_in[11];
    const float* Winb  = (const float*)d_in[12];
    const float* binb  = (const float*)d_in[13];
    const float* dtbb  = (const float*)d_in[14];
    const float* Alogb = (const float*)d_in[15];
    const float* Db    = (const float*)d_in[16];
    const float* Woutb = (const float*)d_in[17];
    const float* boutb = (const float*)d_in[18];
    const float* W1  = (const float*)d_in[19];
    const float* b1m = (const float*)d_in[20];
    const float* bng = (const float*)d_in[21];
    const float* bnb = (const float*)d_in[22];
    const float* W2  = (const float*)d_in[23];
    const float* b2m = (const float*)d_in[24];
    float* out = (float*)d_out;

    float* xln   = sym(g_xln);
    float* projf = sym(g_projf);
    float* projb = sym(g_projb);
    float* gated = sym(g_gated);
    float* x2    = sym(g_x2);
    float* h2    = sym(g_h2);
    float* hid   = sym(g_hid);
    float* wcat  = sym(g_wcat);
    float* bcat  = sym(g_bcat);

    // 1. LN1
    ln_kernel<<<M_, 128>>>(points, g1, be1, xln);

    // 1b. stack output-proj weights on K (enables single fused out GEMM)
    prep_wcat<<<(DI_ * C_ + 255) / 256, 256>>>(Woutf, Woutb, boutf, boutb, wcat, bcat);

    // 2/3. input projections (N=1676, guarded NN path)
    dim3 gproj((PROJ_ + BN - 1) / BN, M_ / BM);
    gemm_kernel<false, 0><<<gproj, 256>>>(xln, Winf, binf, projf, M_, PROJ_, C_, nullptr, nullptr);
    gemm_kernel<false, 0><<<gproj, 256>>>(xln, Winb, binb, projb, M_, PROJ_, C_, nullptr, nullptr);

    // 4. bidirectional scan + gating -> combined gated buffer
    scan_kernel<<<2 * B_ * H_, 256>>>(projf, projb, dtbf, Alogf, Df,
                                      dtbb, Alogb, Db, gated);

    // 5. fused output projection (K-concat) + residual -> x2
    dim3 gwout(C_ / BN, M_ / BM);
    gemm_kernel<false, 2><<<gwout, 256>>>(gated, wcat, bcat, x2, M_, C_, DI2_, points, nullptr);

    // 6. LN2
    ln_kernel<<<M_, 128>>>(x2, g2, be2, h2);

    // 7. MLP up: h2 @ W1^T, *bn, +bnb, relu
    dim3 gmlp1(HID_ / BN, M_ / BM);
    gemm_kernel<true, 1><<<gmlp1, 256>>>(h2, W1, b1m, hid, M_, HID_, C_, bng, bnb);

    // 8. MLP down: hid @ W2^T + b2m + x2 -> d_out
    dim3 gmlp2(C_ / BN, M_ / BM);
    gemm_kernel<true, 2><<<gmlp2, 256>>>(hid, W2, b2m, out, M_, C_, HID_, x2, nullptr);
}

// round 4
// speedup vs baseline: 1.8810x; 1.5226x over previous
#include <cuda_runtime.h>
#include <cuda_bf16.h>
#include <math.h>

// ---------------- problem constants ----------------
#define B_   4
#define L_   2048
#define C_   384
#define H_   12
#define N_   64
#define DI_  768
#define DI2_ 1536
#define HID_ 1536
#define PROJ_ 1676          // 2*DI + 2*N + H
#define M_   (B_*L_)        // 8192
#define EPS_ 1e-5f

#define Q_    64            // chunk length
#define NC_   32            // chunks per sequence (L/Q)
#define NBLK_ (2*B_*H_*NC_) // 3072

// ---------------- scratch (no allocations allowed) ----------------
__device__ float g_xln  [M_*C_];
__device__ float g_projf[M_*PROJ_];
__device__ float g_projb[M_*PROJ_];
__device__ float g_gated[M_*DI2_];     // [fwd(768) | bwd(768)] per row
__device__ float g_x2   [M_*C_];
__device__ float g_h2   [M_*C_];
__device__ float g_hid  [M_*HID_];
__device__ float g_wcat [DI2_*C_];     // [Woutf ; Woutb] stacked on K
__device__ float g_bcat [C_];
__device__ float g_ST   [(size_t)NBLK_*64*64];  // per-chunk state contribution [n][d]
__device__ float g_hp   [(size_t)NBLK_*64*64];  // state entering each chunk [n][d]
__device__ float g_dts  [NBLK_*Q_];
__device__ float g_css  [NBLK_*Q_];
__device__ float g_dtsum[NBLK_];

// ---------------- block reduction (128 threads) ----------------
__device__ __forceinline__ float blockSum128(float v) {
    __shared__ float sh[4];
    int lane = threadIdx.x & 31, w = threadIdx.x >> 5;
    #pragma unroll
    for (int o = 16; o; o >>= 1) v += __shfl_xor_sync(0xffffffffu, v, o);
    if (lane == 0) sh[w] = v;
    __syncthreads();
    float r = sh[0] + sh[1] + sh[2] + sh[3];
    __syncthreads();
    return r;
}

// ---------------- LayerNorm (row of 384) ----------------
__global__ void ln_kernel(const float* __restrict__ x,
                          const float* __restrict__ g,
                          const float* __restrict__ be,
                          float* __restrict__ o) {
    size_t row = blockIdx.x;
    const float* xr = x + row * C_;
    int t = threadIdx.x;
    float v0 = xr[t], v1 = xr[t + 128], v2 = xr[t + 256];
    float mu = blockSum128(v0 + v1 + v2) * (1.f / C_);
    float d0 = v0 - mu, d1 = v1 - mu, d2 = v2 - mu;
    float var = blockSum128(d0*d0 + d1*d1 + d2*d2) * (1.f / C_);
    float inv = rsqrtf(var + EPS_);
    float* orow = o + row * C_;
    orow[t]       = d0 * inv * g[t]       + be[t];
    orow[t + 128] = d1 * inv * g[t + 128] + be[t + 128];
    orow[t + 256] = d2 * inv * g[t + 256] + be[t + 256];
}

// ---------------- weight concat for fused output projection ----------------
__global__ void prep_wcat(const float* __restrict__ Wf, const float* __restrict__ Wb,
                          const float* __restrict__ bf, const float* __restrict__ bb,
                          float* __restrict__ Wcat, float* __restrict__ bcat) {
    int i = blockIdx.x * 256 + threadIdx.x;
    if (i < DI_ * C_) {
        Wcat[i] = Wf[i];
        Wcat[DI_ * C_ + i] = Wb[i];
    }
    if (i < C_) bcat[i] = bf[i] + bb[i];
}

// ---------------- tiled fp32 GEMM: 128x128x16, 8x8/thread, double buffered ----
#define BM 128
#define BN 128
#define BK 16

template<bool BT, int EPI>
__global__ __launch_bounds__(256, 2)
void gemm_kernel(const float* __restrict__ A, const float* __restrict__ Bm,
                 const float* __restrict__ bias, float* __restrict__ C,
                 int M, int N, int K,
                 const float* __restrict__ e1, const float* __restrict__ e2) {
    __shared__ float As[2][BK][BM + 4];
    __shared__ float Bs[2][BK][BN + 4];
    int tid = threadIdx.x;
    int tx = tid & 15, ty = tid >> 4;
    int gm0 = blockIdx.y * BM, gn0 = blockIdx.x * BN;

    int ar = tid >> 2;
    int ac = (tid & 3) << 2;
    int bk = tid >> 4;
    int bn = (tid & 15) << 2;

    float4 a0, a1, b0, b1;
    const float4 z4 = {0.f, 0.f, 0.f, 0.f};

    {
        const float* Ap = A + (size_t)(gm0 + ar) * K + ac;
        a0 = *(const float4*)(Ap);
        a1 = *(const float4*)(Ap + (size_t)64 * K);
        if (BT) {
            const float* Bp = Bm + (size_t)(gn0 + ar) * K + ac;
            b0 = *(const float4*)(Bp);
            b1 = *(const float4*)(Bp + (size_t)64 * K);
        } else {
            int n0 = gn0 + bn;
            const float* Bp = Bm + (size_t)bk * N;
            b0 = (n0 < N) ? *(const float4*)(Bp + n0) : z4;
            b1 = (n0 + 64 < N) ? *(const float4*)(Bp + n0 + 64) : z4;
        }
    }
    As[0][ac+0][ar] = a0.x; As[0][ac+1][ar] = a0.y; As[0][ac+2][ar] = a0.z; As[0][ac+3][ar] = a0.w;
    As[0][ac+0][ar+64] = a1.x; As[0][ac+1][ar+64] = a1.y; As[0][ac+2][ar+64] = a1.z; As[0][ac+3][ar+64] = a1.w;
    if (BT) {
        Bs[0][ac+0][ar] = b0.x; Bs[0][ac+1][ar] = b0.y; Bs[0][ac+2][ar] = b0.z; Bs[0][ac+3][ar] = b0.w;
        Bs[0][ac+0][ar+64] = b1.x; Bs[0][ac+1][ar+64] = b1.y; Bs[0][ac+2][ar+64] = b1.z; Bs[0][ac+3][ar+64] = b1.w;
    } else {
        *(float4*)&Bs[0][bk][bn] = b0;
        *(float4*)&Bs[0][bk][bn + 64] = b1;
    }
    __syncthreads();

    float acc[8][8];
    #pragma unroll
    for (int i = 0; i < 8; i++)
        #pragma unroll
        for (int j = 0; j < 8; j++) acc[i][j] = 0.f;

    int nkt = K / BK;
    int buf = 0;
    for (int kt = 0; kt < nkt; ++kt) {
        if (kt + 1 < nkt) {
            int gk = (kt + 1) * BK;
            const float* Ap = A + (size_t)(gm0 + ar) * K + gk + ac;
            a0 = *(const float4*)(Ap);
            a1 = *(const float4*)(Ap + (size_t)64 * K);
            if (BT) {
                const float* Bp = Bm + (size_t)(gn0 + ar) * K + gk + ac;
                b0 = *(const float4*)(Bp);
                b1 = *(const float4*)(Bp + (size_t)64 * K);
            } else {
                int n0 = gn0 + bn;
                const float* Bp = Bm + (size_t)(gk + bk) * N;
                b0 = (n0 < N) ? *(const float4*)(Bp + n0) : z4;
                b1 = (n0 + 64 < N) ? *(const float4*)(Bp + n0 + 64) : z4;
            }
        }
        #pragma unroll
        for (int kk = 0; kk < BK; ++kk) {
            float4 x0 = *(const float4*)&As[buf][kk][ty * 4];
            float4 x1 = *(const float4*)&As[buf][kk][ty * 4 + 64];
            float4 y0 = *(const float4*)&Bs[buf][kk][tx * 4];
            float4 y1 = *(const float4*)&Bs[buf][kk][tx * 4 + 64];
            float av[8] = {x0.x, x0.y, x0.z, x0.w, x1.x, x1.y, x1.z, x1.w};
            float bv[8] = {y0.x, y0.y, y0.z, y0.w, y1.x, y1.y, y1.z, y1.w};
            #pragma unroll
            for (int i = 0; i < 8; i++)
                #pragma unroll
                for (int j = 0; j < 8; j++)
                    acc[i][j] = fmaf(av[i], bv[j], acc[i][j]);
        }
        if (kt + 1 < nkt) {
            int nb2 = buf ^ 1;
            As[nb2][ac+0][ar] = a0.x; As[nb2][ac+1][ar] = a0.y; As[nb2][ac+2][ar] = a0.z; As[nb2][ac+3][ar] = a0.w;
            As[nb2][ac+0][ar+64] = a1.x; As[nb2][ac+1][ar+64] = a1.y; As[nb2][ac+2][ar+64] = a1.z; As[nb2][ac+3][ar+64] = a1.w;
            if (BT) {
                Bs[nb2][ac+0][ar] = b0.x; Bs[nb2][ac+1][ar] = b0.y; Bs[nb2][ac+2][ar] = b0.z; Bs[nb2][ac+3][ar] = b0.w;
                Bs[nb2][ac+0][ar+64] = b1.x; Bs[nb2][ac+1][ar+64] = b1.y; Bs[nb2][ac+2][ar+64] = b1.z; Bs[nb2][ac+3][ar+64] = b1.w;
            } else {
                *(float4*)&Bs[nb2][bk][bn] = b0;
                *(float4*)&Bs[nb2][bk][bn + 64] = b1;
            }
            __syncthreads();
            buf ^= 1;
        }
    }

    const float bnrs = rsqrtf(1.f + EPS_);
    #pragma unroll
    for (int ih = 0; ih < 2; ih++) {
        #pragma unroll
        for (int i = 0; i < 4; i++) {
            int m = gm0 + ty * 4 + i + ih * 64;
            #pragma unroll
            for (int jh = 0; jh < 2; jh++) {
                int n = gn0 + tx * 4 + jh * 64;
                if (n < N) {
                    float* accr = &acc[ih * 4 + i][jh * 4];
                    float4 v;
                    float4 bs4 = *(const float4*)(bias + n);
                    v.x = accr[0] + bs4.x; v.y = accr[1] + bs4.y;
                    v.z = accr[2] + bs4.z; v.w = accr[3] + bs4.w;
                    if (EPI == 1) {
                        float4 s4 = *(const float4*)(e1 + n);
                        float4 t4 = *(const float4*)(e2 + n);
                        v.x = fmaxf(v.x * (s4.x * bnrs) + t4.x, 0.f);
                        v.y = fmaxf(v.y * (s4.y * bnrs) + t4.y, 0.f);
                        v.z = fmaxf(v.z * (s4.z * bnrs) + t4.z, 0.f);
                        v.w = fmaxf(v.w * (s4.w * bnrs) + t4.w, 0.f);
                    } else if (EPI == 2) {
                        float4 r4 = *(const float4*)(e1 + (size_t)m * N + n);
                        v.x += r4.x; v.y += r4.y; v.z += r4.z; v.w += r4.w;
                    }
                    *(float4*)(C + (size_t)m * N + n) = v;
                }
            }
        }
    }
}

// ============ chunked selective scan ============
// blk = ((dir*B + b)*H + h)*NC + c

// ---- kernel A: per-chunk dt/cumsum + state contribution S^T[n][d] ----
__global__ __launch_bounds__(256)
void chunk_state_kernel(const float* __restrict__ projf, const float* __restrict__ projb,
                        const float* __restrict__ dtbf, const float* __restrict__ Alogf,
                        const float* __restrict__ dtbb, const float* __restrict__ Alogb,
                        float* __restrict__ ST, float* __restrict__ dts,
                        float* __restrict__ css, float* __restrict__ dtsum) {
    int blk = blockIdx.x;
    int c   = blk & (NC_ - 1);
    int h   = (blk >> 5) % H_;
    int b   = (blk / (NC_ * H_)) & (B_ - 1);
    int dir = blk / (NC_ * H_ * B_);
    const float* proj = dir ? projb : projf;
    float A    = -expf((dir ? Alogb : Alogf)[h]);
    float dtbh = (dir ? dtbb : dtbf)[h];

    __shared__ float Bsm[Q_ * 65];
    __shared__ float Xw [Q_ * 65];
    __shared__ float dsh[Q_], csh[Q_];

    int tid = threadIdx.x;
    if (tid < Q_) {
        int p = c * Q_ + tid;
        int l = dir ? (L_ - 1 - p) : p;
        float raw = proj[(size_t)(b * L_ + l) * PROJ_ + 2*DI_ + 2*N_ + h] + dtbh;
        float dt = (raw > 20.f) ? raw : log1pf(__expf(raw));
        dsh[tid] = dt;
        csh[tid] = dt;
    }
    __syncthreads();
    // inclusive scan over 64 (Hillis-Steele)
    for (int off = 1; off < Q_; off <<= 1) {
        float v = 0.f;
        if (tid < Q_ && tid >= off) v = csh[tid - off];
        __syncthreads();
        if (tid < Q_ && tid >= off) csh[tid] += v;
        __syncthreads();
    }
    float cend = csh[Q_ - 1];
    if (tid < Q_) {
        dts[blk * Q_ + tid] = dsh[tid];
        css[blk * Q_ + tid] = csh[tid];
    }
    if (tid == 0) dtsum[blk] = cend;

    // load B and decay-weighted X
    #pragma unroll
    for (int i = 0; i < 4; i++) {
        int s  = (tid >> 4) + i * 16;
        int c4 = (tid & 15) << 2;
        int p = c * Q_ + s;
        int l = dir ? (L_ - 1 - p) : p;
        const float* row = proj + (size_t)(b * L_ + l) * PROJ_;
        float4 bb = *(const float4*)(row + 2*DI_ + c4);
        float4 xx = *(const float4*)(row + DI_ + h*64 + c4);
        float w = __expf(A * (cend - csh[s])) * dsh[s];
        float* Bp = Bsm + s * 65 + c4;
        Bp[0] = bb.x; Bp[1] = bb.y; Bp[2] = bb.z; Bp[3] = bb.w;
        float* Xp = Xw + s * 65 + c4;
        Xp[0] = w * xx.x; Xp[1] = w * xx.y; Xp[2] = w * xx.z; Xp[3] = w * xx.w;
    }
    __syncthreads();

    // S^T[n][d] = sum_s B[s][n] * Xw[s][d]
    int ty = tid >> 4, tx = tid & 15;
    float acc[4][4] = {};
    #pragma unroll 8
    for (int s = 0; s < Q_; s++) {
        float a0 = Bsm[s*65 + ty*4 + 0];
        float a1 = Bsm[s*65 + ty*4 + 1];
        float a2 = Bsm[s*65 + ty*4 + 2];
        float a3 = Bsm[s*65 + ty*4 + 3];
        float b0 = Xw[s*65 + tx*4 + 0];
        float b1 = Xw[s*65 + tx*4 + 1];
        float b2 = Xw[s*65 + tx*4 + 2];
        float b3 = Xw[s*65 + tx*4 + 3];
        acc[0][0] = fmaf(a0,b0,acc[0][0]); acc[0][1] = fmaf(a0,b1,acc[0][1]);
        acc[0][2] = fmaf(a0,b2,acc[0][2]); acc[0][3] = fmaf(a0,b3,acc[0][3]);
        acc[1][0] = fmaf(a1,b0,acc[1][0]); acc[1][1] = fmaf(a1,b1,acc[1][1]);
        acc[1][2] = fmaf(a1,b2,acc[1][2]); acc[1][3] = fmaf(a1,b3,acc[1][3]);
        acc[2][0] = fmaf(a2,b0,acc[2][0]); acc[2][1] = fmaf(a2,b1,acc[2][1]);
        acc[2][2] = fmaf(a2,b2,acc[2][2]); acc[2][3] = fmaf(a2,b3,acc[2][3]);
        acc[3][0] = fmaf(a3,b0,acc[3][0]); acc[3][1] = fmaf(a3,b1,acc[3][1]);
        acc[3][2] = fmaf(a3,b2,acc[3][2]); acc[3][3] = fmaf(a3,b3,acc[3][3]);
    }
    #pragma unroll
    for (int i = 0; i < 4; i++) {
        float4 v = {acc[i][0], acc[i][1], acc[i][2], acc[i][3]};
        *(float4*)(ST + (size_t)blk * 4096 + (ty*4 + i) * 64 + tx*4) = v;
    }
}

// ---- kernel B: sequential pass over 32 chunk states (96 blocks) ----
__global__ __launch_bounds__(256)
void state_pass_kernel(const float* __restrict__ ST, float* __restrict__ hp,
                       const float* __restrict__ dtsum,
                       const float* __restrict__ Alogf, const float* __restrict__ Alogb) {
    int g = blockIdx.x;                 // dir*48 + b*12 + h
    int dir = g / (B_ * H_);
    int h = g % H_;
    float A = -expf((dir ? Alogb : Alogf)[h]);
    int t = threadIdx.x;
    float hreg[16];
    #pragma unroll
    for (int k = 0; k < 16; k++) hreg[k] = 0.f;
    size_t base = (size_t)g * NC_ * 4096;
    for (int cc = 0; cc < NC_; cc++) {
        size_t o = base + (size_t)cc * 4096 + t;
        float al = expf(A * dtsum[g * NC_ + cc]);
        float sv[16];
        #pragma unroll
        for (int k = 0; k < 16; k++) sv[k] = ST[o + k*256];
        #pragma unroll
        for (int k = 0; k < 16; k++) {
            hp[o + k*256] = hreg[k];
            hreg[k] = al * hreg[k] + sv[k];
        }
    }
}

// ---- kernel C: per-chunk output: (M∘(C B^T))X + Λ∘(C h_prev^T) + Dx, gated ----
extern __shared__ float smc[];
__global__ __launch_bounds__(256)
void chunk_out_kernel(const float* __restrict__ projf, const float* __restrict__ projb,
                      const float* __restrict__ Alogf, const float* __restrict__ Alogb,
                      const float* __restrict__ Df, const float* __restrict__ Db,
                      const float* __restrict__ dts, const float* __restrict__ css,
                      const float* __restrict__ hp, float* __restrict__ gated) {
    int blk = blockIdx.x;
    int c   = blk & (NC_ - 1);
    int h   = (blk >> 5) % H_;
    int b   = (blk / (NC_ * H_)) & (B_ - 1);
    int dir = blk / (NC_ * H_ * B_);
    const float* proj = dir ? projb : projf;
    const float* Dv   = dir ? Db : Df;
    float A = -expf((dir ? Alogb : Alogf)[h]);

    float* Csm = smc;                 // [t][n]
    float* Buf = smc + 64*65;         // B -> Gm -> H
    float* Xsm = smc + 2*64*65;       // [s][d]
    float* dsh = smc + 3*64*65;
    float* csh = dsh + 64;

    int tid = threadIdx.x;
    if (tid < Q_) {
        dsh[tid] = dts[blk * Q_ + tid];
        csh[tid] = css[blk * Q_ + tid];
    }
    #pragma unroll
    for (int i = 0; i < 4; i++) {
        int s  = (tid >> 4) + i * 16;
        int c4 = (tid & 15) << 2;
        int p = c * Q_ + s;
        int l = dir ? (L_ - 1 - p) : p;
        const float* row = proj + (size_t)(b * L_ + l) * PROJ_;
        float4 cc4 = *(const float4*)(row + 2*DI_ + N_ + c4);
        float4 bb4 = *(const float4*)(row + 2*DI_ + c4);
        float4 xx4 = *(const float4*)(row + DI_ + h*64 + c4);
        float* Cp = Csm + s*65 + c4;
        Cp[0] = cc4.x; Cp[1] = cc4.y; Cp[2] = cc4.z; Cp[3] = cc4.w;
        float* Bp = Buf + s*65 + c4;
        Bp[0] = bb4.x; Bp[1] = bb4.y; Bp[2] = bb4.z; Bp[3] = bb4.w;
        float* Xp = Xsm + s*65 + c4;
        Xp[0] = xx4.x; Xp[1] = xx4.y; Xp[2] = xx4.z; Xp[3] = xx4.w;
    }
    __syncthreads();

    int ty = tid >> 4, tx = tid & 15;

    // phase 1: G[t][s] = sum_n C[t][n] * B[s][n]
    float acc[4][4] = {};
    #pragma unroll 8
    for (int n = 0; n < 64; n++) {
        float a0 = Csm[(ty*4+0)*65 + n];
        float a1 = Csm[(ty*4+1)*65 + n];
        float a2 = Csm[(ty*4+2)*65 + n];
        float a3 = Csm[(ty*4+3)*65 + n];
        float b0 = Buf[(tx*4+0)*65 + n];
        float b1 = Buf[(tx*4+1)*65 + n];
        float b2 = Buf[(tx*4+2)*65 + n];
        float b3 = Buf[(tx*4+3)*65 + n];
        acc[0][0]=fmaf(a0,b0,acc[0][0]); acc[0][1]=fmaf(a0,b1,acc[0][1]);
        acc[0][2]=fmaf(a0,b2,acc[0][2]); acc[0][3]=fmaf(a0,b3,acc[0][3]);
        acc[1][0]=fmaf(a1,b0,acc[1][0]); acc[1][1]=fmaf(a1,b1,acc[1][1]);
        acc[1][2]=fmaf(a1,b2,acc[1][2]); acc[1][3]=fmaf(a1,b3,acc[1][3]);
        acc[2][0]=fmaf(a2,b0,acc[2][0]); acc[2][1]=fmaf(a2,b1,acc[2][1]);
        acc[2][2]=fmaf(a2,b2,acc[2][2]); acc[2][3]=fmaf(a2,b3,acc[2][3]);
        acc[3][0]=fmaf(a3,b0,acc[3][0]); acc[3][1]=fmaf(a3,b1,acc[3][1]);
        acc[3][2]=fmaf(a3,b2,acc[3][2]); acc[3][3]=fmaf(a3,b3,acc[3][3]);
    }
    __syncthreads();   // B reads done -> reuse Buf for masked G

    #pragma unroll
    for (int i = 0; i < 4; i++) {
        int t_ = ty*4 + i;
        #pragma unroll
        for (int j = 0; j < 4; j++) {
            int s_ = tx*4 + j;
            float m = (s_ <= t_) ? __expf(A * (csh[t_] - csh[s_])) * dsh[s_] : 0.f;
            Buf[t_*65 + s_] = acc[i][j] * m;
        }
    }
    __syncthreads();

    // phase 2: Y1[t][d] = sum_s Gm[t][s] * X[s][d]
    float y1[4][4] = {};
    #pragma unroll 8
    for (int s = 0; s < 64; s++) {
        float a0 = Buf[(ty*4+0)*65 + s];
        float a1 = Buf[(ty*4+1)*65 + s];
        float a2 = Buf[(ty*4+2)*65 + s];
        float a3 = Buf[(ty*4+3)*65 + s];
        float b0 = Xsm[s*65 + tx*4 + 0];
        float b1 = Xsm[s*65 + tx*4 + 1];
        float b2 = Xsm[s*65 + tx*4 + 2];
        float b3 = Xsm[s*65 + tx*4 + 3];
        y1[0][0]=fmaf(a0,b0,y1[0][0]); y1[0][1]=fmaf(a0,b1,y1[0][1]);
        y1[0][2]=fmaf(a0,b2,y1[0][2]); y1[0][3]=fmaf(a0,b3,y1[0][3]);
        y1[1][0]=fmaf(a1,b0,y1[1][0]); y1[1][1]=fmaf(a1,b1,y1[1][1]);
        y1[1][2]=fmaf(a1,b2,y1[1][2]); y1[1][3]=fmaf(a1,b3,y1[1][3]);
        y1[2][0]=fmaf(a2,b0,y1[2][0]); y1[2][1]=fmaf(a2,b1,y1[2][1]);
        y1[2][2]=fmaf(a2,b2,y1[2][2]); y1[2][3]=fmaf(a2,b3,y1[2][3]);
        y1[3][0]=fmaf(a3,b0,y1[3][0]); y1[3][1]=fmaf(a3,b1,y1[3][1]);
        y1[3][2]=fmaf(a3,b2,y1[3][2]); y1[3][3]=fmaf(a3,b3,y1[3][3]);
    }
    __syncthreads();   // Gm done -> reuse Buf for h_prev

    #pragma unroll
    for (int i = 0; i < 4; i++) {
        int n  = (tid >> 4) + i * 16;
        int c4 = (tid & 15) << 2;
        float4 hh = *(const float4*)(hp + (size_t)blk * 4096 + n*64 + c4);
        float* Hp = Buf + n*65 + c4;
        Hp[0] = hh.x; Hp[1] = hh.y; Hp[2] = hh.z; Hp[3] = hh.w;
    }
    __syncthreads();

    // phase 3: Y2[t][d] = sum_n C[t][n] * H[n][d]
    float y2[4][4] = {};
    #pragma unroll 8
    for (int n = 0; n < 64; n++) {
        float a0 = Csm[(ty*4+0)*65 + n];
        float a1 = Csm[(ty*4+1)*65 + n];
        float a2 = Csm[(ty*4+2)*65 + n];
        float a3 = Csm[(ty*4+3)*65 + n];
        float b0 = Buf[n*65 + tx*4 + 0];
        float b1 = Buf[n*65 + tx*4 + 1];
        float b2 = Buf[n*65 + tx*4 + 2];
        float b3 = Buf[n*65 + tx*4 + 3];
        y2[0][0]=fmaf(a0,b0,y2[0][0]); y2[0][1]=fmaf(a0,b1,y2[0][1]);
        y2[0][2]=fmaf(a0,b2,y2[0][2]); y2[0][3]=fmaf(a0,b3,y2[0][3]);
        y2[1][0]=fmaf(a1,b0,y2[1][0]); y2[1][1]=fmaf(a1,b1,y2[1][1]);
        y2[1][2]=fmaf(a1,b2,y2[1][2]); y2[1][3]=fmaf(a1,b3,y2[1][3]);
        y2[2][0]=fmaf(a2,b0,y2[2][0]); y2[2][1]=fmaf(a2,b1,y2[2][1]);
        y2[2][2]=fmaf(a2,b2,y2[2][2]); y2[2][3]=fmaf(a2,b3,y2[2][3]);
        y2[3][0]=fmaf(a3,b0,y2[3][0]); y2[3][1]=fmaf(a3,b1,y2[3][1]);
        y2[3][2]=fmaf(a3,b2,y2[3][2]); y2[3][3]=fmaf(a3,b3,y2[3][3]);
    }

    // epilogue: + D*x, gate with silu(z), write to combined gated buffer
    float d0 = Dv[h*64 + tx*4 + 0];
    float d1 = Dv[h*64 + tx*4 + 1];
    float d2 = Dv[h*64 + tx*4 + 2];
    float d3 = Dv[h*64 + tx*4 + 3];
    #pragma unroll
    for (int i = 0; i < 4; i++) {
        int t_ = ty*4 + i;
        int p = c * Q_ + t_;
        int l = dir ? (L_ - 1 - p) : p;
        float lam = __expf(A * csh[t_]);
        const float* row = proj + (size_t)(b * L_ + l) * PROJ_;
        float4 zz = *(const float4*)(row + h*64 + tx*4);
        float xr0 = Xsm[t_*65 + tx*4 + 0];
        float xr1 = Xsm[t_*65 + tx*4 + 1];
        float xr2 = Xsm[t_*65 + tx*4 + 2];
        float xr3 = Xsm[t_*65 + tx*4 + 3];
        float4 o;
        float yv;
        yv = y1[i][0] + lam * y2[i][0] + d0 * xr0;
        o.x = yv * (zz.x / (1.f + __expf(-zz.x)));
        yv = y1[i][1] + lam * y2[i][1] + d1 * xr1;
        o.y = yv * (zz.y / (1.f + __expf(-zz.y)));
        yv = y1[i][2] + lam * y2[i][2] + d2 * xr2;
        o.z = yv * (zz.z / (1.f + __expf(-zz.z)));
        yv = y1[i][3] + lam * y2[i][3] + d3 * xr3;
        o.w = yv * (zz.w / (1.f + __expf(-zz.w)));
        *(float4*)(gated + (size_t)(b * L_ + l) * DI2_ + dir*DI_ + h*64 + tx*4) = o;
    }
}

// ---------------- host launch ----------------
static float* sym(const void* s) {
    void* p = nullptr;
    cudaGetSymbolAddress(&p, s);
    return (float*)p;
}

extern "C" void kernel_launch(void* const* d_in, const int* in_sizes, int n_in,
                              void* d_out, int out_size) {
    const float* points = (const float*)d_in[0];
    const float* g1  = (const float*)d_in[1];
    const float* be1 = (const float*)d_in[2];
    const float* g2  = (const float*)d_in[3];
    const float* be2 = (const float*)d_in[4];
    const float* Winf  = (const float*)d_in[5];
    const float* binf  = (const float*)d_in[6];
    const float* dtbf  = (const float*)d_in[7];
    const float* Alogf = (const float*)d_in[8];
    const float* Df    = (const float*)d_in[9];
    const float* Woutf = (const float*)d_in[10];
    const float* boutf = (const float*)d_in[11];
    const float* Winb  = (const float*)d_in[12];
    const float* binb  = (const float*)d_in[13];
    const float* dtbb  = (const float*)d_in[14];
    const float* Alogb = (const float*)d_in[15];
    const float* Db    = (const float*)d_in[16];
    const float* Woutb = (const float*)d_in[17];
    const float* boutb = (const float*)d_in[18];
    const float* W1  = (const float*)d_in[19];
    const float* b1m = (const float*)d_in[20];
    const float* bng = (const float*)d_in[21];
    const float* bnb = (const float*)d_in[22];
    const float* W2  = (const float*)d_in[23];
    const float* b2m = (const float*)d_in[24];
    float* out = (float*)d_out;

    float* xln   = sym(g_xln);
    float* projf = sym(g_projf);
    float* projb = sym(g_projb);
    float* gated = sym(g_gated);
    float* x2    = sym(g_x2);
    float* h2    = sym(g_h2);
    float* hid   = sym(g_hid);
    float* wcat  = sym(g_wcat);
    float* bcat  = sym(g_bcat);
    float* ST    = sym(g_ST);
    float* hp    = sym(g_hp);
    float* dts   = sym(g_dts);
    float* css   = sym(g_css);
    float* dtsum = sym(g_dtsum);

    int smemC = (3 * 64 * 65 + 128) * sizeof(float);
    cudaFuncSetAttribute(chunk_out_kernel, cudaFuncAttributeMaxDynamicSharedMemorySize, smemC);

    // 1. LN1
    ln_kernel<<<M_, 128>>>(points, g1, be1, xln);

    // 1b. stack output-proj weights on K
    prep_wcat<<<(DI_ * C_ + 255) / 256, 256>>>(Woutf, Woutb, boutf, boutb, wcat, bcat);

    // 2/3. input projections
    dim3 gproj((PROJ_ + BN - 1) / BN, M_ / BM);
    gemm_kernel<false, 0><<<gproj, 256>>>(xln, Winf, binf, projf, M_, PROJ_, C_, nullptr, nullptr);
    gemm_kernel<false, 0><<<gproj, 256>>>(xln, Winb, binb, projb, M_, PROJ_, C_, nullptr, nullptr);

    // 4. chunked bidirectional scan
    chunk_state_kernel<<<NBLK_, 256>>>(projf, projb, dtbf, Alogf, dtbb, Alogb,
                                       ST, dts, css, dtsum);
    state_pass_kernel<<<2 * B_ * H_, 256>>>(ST, hp, dtsum, Alogf, Alogb);
    chunk_out_kernel<<<NBLK_, 256, smemC>>>(projf, projb, Alogf, Alogb, Df, Db,
                                            dts, css, hp, gated);

    // 5. fused output projection (K-concat) + residual -> x2
    dim3 gwout(C_ / BN, M_ / BM);
    gemm_kernel<false, 2><<<gwout, 256>>>(gated, wcat, bcat, x2, M_, C_, DI2_, points, nullptr);

    // 6. LN2
    ln_kernel<<<M_, 128>>>(x2, g2, be2, h2);

    // 7. MLP up
    dim3 gmlp1(HID_ / BN, M_ / BM);
    gemm_kernel<true, 1><<<gmlp1, 256>>>(h2, W1, b1m, hid, M_, HID_, C_, bng, bnb);

    // 8. MLP down + residual -> d_out
    dim3 gmlp2(C_ / BN, M_ / BM);
    gemm_kernel<true, 2><<<gmlp2, 256>>>(hid, W2, b2m, out, M_, C_, HID_, x2, nullptr);
}

// round 5
// speedup vs baseline: 1.8814x; 1.0002x over previous
#include <cuda_runtime.h>
#include <cuda_bf16.h>
#include <math.h>

// ---------------- problem constants ----------------
#define B_   4
#define L_   2048
#define C_   384
#define H_   12
#define N_   64
#define DI_  768
#define DI2_ 1536
#define HID_ 1536
#define PROJ_ 1676          // 2*DI + 2*N + H
#define M_   (B_*L_)        // 8192
#define EPS_ 1e-5f

#define Q_    64            // chunk length
#define NC_   32            // chunks per sequence (L/Q)
#define NBLK_ (2*B_*H_*NC_) // 3072

// ---------------- scratch (no allocations allowed) ----------------
__device__ float g_xln  [M_*C_];
__device__ float g_projf[M_*PROJ_];
__device__ float g_projb[M_*PROJ_];
__device__ float g_gated[M_*DI2_];     // [fwd(768) | bwd(768)] per row
__device__ float g_x2   [M_*C_];
__device__ float g_h2   [M_*C_];
__device__ float g_hid  [M_*HID_];
__device__ float g_wcat [DI2_*C_];     // [Woutf ; Woutb] stacked on K
__device__ float g_bcat [C_];
__device__ float g_ST   [(size_t)NBLK_*64*64];  // per-chunk state contribution [n][d]
__device__ float g_hp   [(size_t)NBLK_*64*64];  // state entering each chunk [n][d]
__device__ float g_dts  [NBLK_*Q_];
__device__ float g_css  [NBLK_*Q_];
__device__ float g_dtsum[NBLK_];

// ---------------- block reduction (128 threads) ----------------
__device__ __forceinline__ float blockSum128(float v) {
    __shared__ float sh[4];
    int lane = threadIdx.x & 31, w = threadIdx.x >> 5;
    #pragma unroll
    for (int o = 16; o; o >>= 1) v += __shfl_xor_sync(0xffffffffu, v, o);
    if (lane == 0) sh[w] = v;
    __syncthreads();
    float r = sh[0] + sh[1] + sh[2] + sh[3];
    __syncthreads();
    return r;
}

// ---------------- LayerNorm (row of 384) ----------------
__global__ void ln_kernel(const float* __restrict__ x,
                          const float* __restrict__ g,
                          const float* __restrict__ be,
                          float* __restrict__ o) {
    size_t row = blockIdx.x;
    const float* xr = x + row * C_;
    int t = threadIdx.x;
    float v0 = xr[t], v1 = xr[t + 128], v2 = xr[t + 256];
    float mu = blockSum128(v0 + v1 + v2) * (1.f / C_);
    float d0 = v0 - mu, d1 = v1 - mu, d2 = v2 - mu;
    float var = blockSum128(d0*d0 + d1*d1 + d2*d2) * (1.f / C_);
    float inv = rsqrtf(var + EPS_);
    float* orow = o + row * C_;
    orow[t]       = d0 * inv * g[t]       + be[t];
    orow[t + 128] = d1 * inv * g[t + 128] + be[t + 128];
    orow[t + 256] = d2 * inv * g[t + 256] + be[t + 256];
}

// ---------------- weight concat for fused output projection ----------------
__global__ void prep_wcat(const float* __restrict__ Wf, const float* __restrict__ Wb,
                          const float* __restrict__ bf, const float* __restrict__ bb,
                          float* __restrict__ Wcat, float* __restrict__ bcat) {
    int i = blockIdx.x * 256 + threadIdx.x;
    if (i < DI_ * C_) {
        Wcat[i] = Wf[i];
        Wcat[DI_ * C_ + i] = Wb[i];
    }
    if (i < C_) bcat[i] = bf[i] + bb[i];
}

// ---------------- tiled fp32 GEMM: 128x128x16, 8x8/thread, double buffered ----
#define BM 128
#define BN 128
#define BK 16

template<bool BT, int EPI>
__global__ __launch_bounds__(256, 2)
void gemm_kernel(const float* __restrict__ A, const float* __restrict__ Bm,
                 const float* __restrict__ bias, float* __restrict__ C,
                 int M, int N, int K,
                 const float* __restrict__ e1, const float* __restrict__ e2) {
    __shared__ float As[2][BK][BM + 4];
    __shared__ float Bs[2][BK][BN + 4];
    int tid = threadIdx.x;
    int tx = tid & 15, ty = tid >> 4;
    int gm0 = blockIdx.y * BM, gn0 = blockIdx.x * BN;

    int ar = tid >> 2;
    int ac = (tid & 3) << 2;
    int bk = tid >> 4;
    int bn = (tid & 15) << 2;

    float4 a0, a1, b0, b1;
    const float4 z4 = {0.f, 0.f, 0.f, 0.f};

    {
        const float* Ap = A + (size_t)(gm0 + ar) * K + ac;
        a0 = *(const float4*)(Ap);
        a1 = *(const float4*)(Ap + (size_t)64 * K);
        if (BT) {
            const float* Bp = Bm + (size_t)(gn0 + ar) * K + ac;
            b0 = *(const float4*)(Bp);
            b1 = *(const float4*)(Bp + (size_t)64 * K);
        } else {
            int n0 = gn0 + bn;
            const float* Bp = Bm + (size_t)bk * N;
            b0 = (n0 < N) ? *(const float4*)(Bp + n0) : z4;
            b1 = (n0 + 64 < N) ? *(const float4*)(Bp + n0 + 64) : z4;
        }
    }
    As[0][ac+0][ar] = a0.x; As[0][ac+1][ar] = a0.y; As[0][ac+2][ar] = a0.z; As[0][ac+3][ar] = a0.w;
    As[0][ac+0][ar+64] = a1.x; As[0][ac+1][ar+64] = a1.y; As[0][ac+2][ar+64] = a1.z; As[0][ac+3][ar+64] = a1.w;
    if (BT) {
        Bs[0][ac+0][ar] = b0.x; Bs[0][ac+1][ar] = b0.y; Bs[0][ac+2][ar] = b0.z; Bs[0][ac+3][ar] = b0.w;
        Bs[0][ac+0][ar+64] = b1.x; Bs[0][ac+1][ar+64] = b1.y; Bs[0][ac+2][ar+64] = b1.z; Bs[0][ac+3][ar+64] = b1.w;
    } else {
        *(float4*)&Bs[0][bk][bn] = b0;
        *(float4*)&Bs[0][bk][bn + 64] = b1;
    }
    __syncthreads();

    float acc[8][8];
    #pragma unroll
    for (int i = 0; i < 8; i++)
        #pragma unroll
        for (int j = 0; j < 8; j++) acc[i][j] = 0.f;

    int nkt = K / BK;
    int buf = 0;
    for (int kt = 0; kt < nkt; ++kt) {
        if (kt + 1 < nkt) {
            int gk = (kt + 1) * BK;
            const float* Ap = A + (size_t)(gm0 + ar) * K + gk + ac;
            a0 = *(const float4*)(Ap);
            a1 = *(const float4*)(Ap + (size_t)64 * K);
            if (BT) {
                const float* Bp = Bm + (size_t)(gn0 + ar) * K + gk + ac;
                b0 = *(const float4*)(Bp);
                b1 = *(const float4*)(Bp + (size_t)64 * K);
            } else {
                int n0 = gn0 + bn;
                const float* Bp = Bm + (size_t)(gk + bk) * N;
                b0 = (n0 < N) ? *(const float4*)(Bp + n0) : z4;
                b1 = (n0 + 64 < N) ? *(const float4*)(Bp + n0 + 64) : z4;
            }
        }
        #pragma unroll
        for (int kk = 0; kk < BK; ++kk) {
            float4 x0 = *(const float4*)&As[buf][kk][ty * 4];
            float4 x1 = *(const float4*)&As[buf][kk][ty * 4 + 64];
            float4 y0 = *(const float4*)&Bs[buf][kk][tx * 4];
            float4 y1 = *(const float4*)&Bs[buf][kk][tx * 4 + 64];
            float av[8] = {x0.x, x0.y, x0.z, x0.w, x1.x, x1.y, x1.z, x1.w};
            float bv[8] = {y0.x, y0.y, y0.z, y0.w, y1.x, y1.y, y1.z, y1.w};
            #pragma unroll
            for (int i = 0; i < 8; i++)
                #pragma unroll
                for (int j = 0; j < 8; j++)
                    acc[i][j] = fmaf(av[i], bv[j], acc[i][j]);
        }
        if (kt + 1 < nkt) {
            int nb2 = buf ^ 1;
            As[nb2][ac+0][ar] = a0.x; As[nb2][ac+1][ar] = a0.y; As[nb2][ac+2][ar] = a0.z; As[nb2][ac+3][ar] = a0.w;
            As[nb2][ac+0][ar+64] = a1.x; As[nb2][ac+1][ar+64] = a1.y; As[nb2][ac+2][ar+64] = a1.z; As[nb2][ac+3][ar+64] = a1.w;
            if (BT) {
                Bs[nb2][ac+0][ar] = b0.x; Bs[nb2][ac+1][ar] = b0.y; Bs[nb2][ac+2][ar] = b0.z; Bs[nb2][ac+3][ar] = b0.w;
                Bs[nb2][ac+0][ar+64] = b1.x; Bs[nb2][ac+1][ar+64] = b1.y; Bs[nb2][ac+2][ar+64] = b1.z; Bs[nb2][ac+3][ar+64] = b1.w;
            } else {
                *(float4*)&Bs[nb2][bk][bn] = b0;
                *(float4*)&Bs[nb2][bk][bn + 64] = b1;
            }
            __syncthreads();
            buf ^= 1;
        }
    }

    const float bnrs = rsqrtf(1.f + EPS_);
    #pragma unroll
    for (int ih = 0; ih < 2; ih++) {
        #pragma unroll
        for (int i = 0; i < 4; i++) {
            int m = gm0 + ty * 4 + i + ih * 64;
            #pragma unroll
            for (int jh = 0; jh < 2; jh++) {
                int n = gn0 + tx * 4 + jh * 64;
                if (n < N) {
                    float* accr = &acc[ih * 4 + i][jh * 4];
                    float4 v;
                    float4 bs4 = *(const float4*)(bias + n);
                    v.x = accr[0] + bs4.x; v.y = accr[1] + bs4.y;
                    v.z = accr[2] + bs4.z; v.w = accr[3] + bs4.w;
                    if (EPI == 1) {
                        float4 s4 = *(const float4*)(e1 + n);
                        float4 t4 = *(const float4*)(e2 + n);
                        v.x = fmaxf(v.x * (s4.x * bnrs) + t4.x, 0.f);
                        v.y = fmaxf(v.y * (s4.y * bnrs) + t4.y, 0.f);
                        v.z = fmaxf(v.z * (s4.z * bnrs) + t4.z, 0.f);
                        v.w = fmaxf(v.w * (s4.w * bnrs) + t4.w, 0.f);
                    } else if (EPI == 2) {
                        float4 r4 = *(const float4*)(e1 + (size_t)m * N + n);
                        v.x += r4.x; v.y += r4.y; v.z += r4.z; v.w += r4.w;
                    }
                    *(float4*)(C + (size_t)m * N + n) = v;
                }
            }
        }
    }
}

// ============ chunked selective scan ============
// blk = ((dir*B + b)*H + h)*NC + c

// ---- kernel A: per-chunk dt/cumsum + state contribution S^T[n][d] ----
__global__ __launch_bounds__(256)
void chunk_state_kernel(const float* __restrict__ projf, const float* __restrict__ projb,
                        const float* __restrict__ dtbf, const float* __restrict__ Alogf,
                        const float* __restrict__ dtbb, const float* __restrict__ Alogb,
                        float* __restrict__ ST, float* __restrict__ dts,
                        float* __restrict__ css, float* __restrict__ dtsum) {
    int blk = blockIdx.x;
    int c   = blk & (NC_ - 1);
    int h   = (blk >> 5) % H_;
    int b   = (blk / (NC_ * H_)) & (B_ - 1);
    int dir = blk / (NC_ * H_ * B_);
    const float* proj = dir ? projb : projf;
    float A    = -expf((dir ? Alogb : Alogf)[h]);
    float dtbh = (dir ? dtbb : dtbf)[h];

    __shared__ float Bsm[Q_ * 65];
    __shared__ float Xw [Q_ * 65];
    __shared__ float dsh[Q_], csh[Q_];

    int tid = threadIdx.x;
    if (tid < Q_) {
        int p = c * Q_ + tid;
        int l = dir ? (L_ - 1 - p) : p;
        float raw = proj[(size_t)(b * L_ + l) * PROJ_ + 2*DI_ + 2*N_ + h] + dtbh;
        float dt = (raw > 20.f) ? raw : log1pf(__expf(raw));
        dsh[tid] = dt;
        csh[tid] = dt;
    }
    __syncthreads();
    // inclusive scan over 64 (Hillis-Steele)
    for (int off = 1; off < Q_; off <<= 1) {
        float v = 0.f;
        if (tid < Q_ && tid >= off) v = csh[tid - off];
        __syncthreads();
        if (tid < Q_ && tid >= off) csh[tid] += v;
        __syncthreads();
    }
    float cend = csh[Q_ - 1];
    if (tid < Q_) {
        dts[blk * Q_ + tid] = dsh[tid];
        css[blk * Q_ + tid] = csh[tid];
    }
    if (tid == 0) dtsum[blk] = cend;

    // load B and decay-weighted X
    #pragma unroll
    for (int i = 0; i < 4; i++) {
        int s  = (tid >> 4) + i * 16;
        int c4 = (tid & 15) << 2;
        int p = c * Q_ + s;
        int l = dir ? (L_ - 1 - p) : p;
        const float* row = proj + (size_t)(b * L_ + l) * PROJ_;
        float4 bb = *(const float4*)(row + 2*DI_ + c4);
        float4 xx = *(const float4*)(row + DI_ + h*64 + c4);
        float w = __expf(A * (cend - csh[s])) * dsh[s];
        float* Bp = Bsm + s * 65 + c4;
        Bp[0] = bb.x; Bp[1] = bb.y; Bp[2] = bb.z; Bp[3] = bb.w;
        float* Xp = Xw + s * 65 + c4;
        Xp[0] = w * xx.x; Xp[1] = w * xx.y; Xp[2] = w * xx.z; Xp[3] = w * xx.w;
    }
    __syncthreads();

    // S^T[n][d] = sum_s B[s][n] * Xw[s][d]
    int ty = tid >> 4, tx = tid & 15;
    float acc[4][4] = {};
    #pragma unroll 8
    for (int s = 0; s < Q_; s++) {
        float a0 = Bsm[s*65 + ty*4 + 0];
        float a1 = Bsm[s*65 + ty*4 + 1];
        float a2 = Bsm[s*65 + ty*4 + 2];
        float a3 = Bsm[s*65 + ty*4 + 3];
        float b0 = Xw[s*65 + tx*4 + 0];
        float b1 = Xw[s*65 + tx*4 + 1];
        float b2 = Xw[s*65 + tx*4 + 2];
        float b3 = Xw[s*65 + tx*4 + 3];
        acc[0][0] = fmaf(a0,b0,acc[0][0]); acc[0][1] = fmaf(a0,b1,acc[0][1]);
        acc[0][2] = fmaf(a0,b2,acc[0][2]); acc[0][3] = fmaf(a0,b3,acc[0][3]);
        acc[1][0] = fmaf(a1,b0,acc[1][0]); acc[1][1] = fmaf(a1,b1,acc[1][1]);
        acc[1][2] = fmaf(a1,b2,acc[1][2]); acc[1][3] = fmaf(a1,b3,acc[1][3]);
        acc[2][0] = fmaf(a2,b0,acc[2][0]); acc[2][1] = fmaf(a2,b1,acc[2][1]);
        acc[2][2] = fmaf(a2,b2,acc[2][2]); acc[2][3] = fmaf(a2,b3,acc[2][3]);
        acc[3][0] = fmaf(a3,b0,acc[3][0]); acc[3][1] = fmaf(a3,b1,acc[3][1]);
        acc[3][2] = fmaf(a3,b2,acc[3][2]); acc[3][3] = fmaf(a3,b3,acc[3][3]);
    }
    #pragma unroll
    for (int i = 0; i < 4; i++) {
        float4 v = {acc[i][0], acc[i][1], acc[i][2], acc[i][3]};
        *(float4*)(ST + (size_t)blk * 4096 + (ty*4 + i) * 64 + tx*4) = v;
    }
}

// ---- kernel B: sequential pass over 32 chunk states (96 blocks) ----
__global__ __launch_bounds__(256)
void state_pass_kernel(const float* __restrict__ ST, float* __restrict__ hp,
                       const float* __restrict__ dtsum,
                       const float* __restrict__ Alogf, const float* __restrict__ Alogb) {
    int g = blockIdx.x;                 // dir*48 + b*12 + h
    int dir = g / (B_ * H_);
    int h = g % H_;
    float A = -expf((dir ? Alogb : Alogf)[h]);
    int t = threadIdx.x;
    float hreg[16];
    #pragma unroll
    for (int k = 0; k < 16; k++) hreg[k] = 0.f;
    size_t base = (size_t)g * NC_ * 4096;
    for (int cc = 0; cc < NC_; cc++) {
        size_t o = base + (size_t)cc * 4096 + t;
        float al = expf(A * dtsum[g * NC_ + cc]);
        float sv[16];
        #pragma unroll
        for (int k = 0; k < 16; k++) sv[k] = ST[o + k*256];
        #pragma unroll
        for (int k = 0; k < 16; k++) {
            hp[o + k*256] = hreg[k];
            hreg[k] = al * hreg[k] + sv[k];
        }
    }
}

// ---- kernel C: per-chunk output: (M∘(C B^T))X + Λ∘(C h_prev^T) + Dx, gated ----
extern __shared__ float smc[];
__global__ __launch_bounds__(256)
void chunk_out_kernel(const float* __restrict__ projf, const float* __restrict__ projb,
                      const float* __restrict__ Alogf, const float* __restrict__ Alogb,
                      const float* __restrict__ Df, const float* __restrict__ Db,
                      const float* __restrict__ dts, const float* __restrict__ css,
                      const float* __restrict__ hp, float* __restrict__ gated) {
    int blk = blockIdx.x;
    int c   = blk & (NC_ - 1);
    int h   = (blk >> 5) % H_;
    int b   = (blk / (NC_ * H_)) & (B_ - 1);
    int dir = blk / (NC_ * H_ * B_);
    const float* proj = dir ? projb : projf;
    const float* Dv   = dir ? Db : Df;
    float A = -expf((dir ? Alogb : Alogf)[h]);

    float* Csm = smc;                 // [t][n]
    float* Buf = smc + 64*65;         // B -> Gm -> H
    float* Xsm = smc + 2*64*65;       // [s][d]
    float* dsh = smc + 3*64*65;
    float* csh = dsh + 64;

    int tid = threadIdx.x;
    if (tid < Q_) {
        dsh[tid] = dts[blk * Q_ + tid];
        csh[tid] = css[blk * Q_ + tid];
    }
    #pragma unroll
    for (int i = 0; i < 4; i++) {
        int s  = (tid >> 4) + i * 16;
        int c4 = (tid & 15) << 2;
        int p = c * Q_ + s;
        int l = dir ? (L_ - 1 - p) : p;
        const float* row = proj + (size_t)(b * L_ + l) * PROJ_;
        float4 cc4 = *(const float4*)(row + 2*DI_ + N_ + c4);
        float4 bb4 = *(const float4*)(row + 2*DI_ + c4);
        float4 xx4 = *(const float4*)(row + DI_ + h*64 + c4);
        float* Cp = Csm + s*65 + c4;
        Cp[0] = cc4.x; Cp[1] = cc4.y; Cp[2] = cc4.z; Cp[3] = cc4.w;
        float* Bp = Buf + s*65 + c4;
        Bp[0] = bb4.x; Bp[1] = bb4.y; Bp[2] = bb4.z; Bp[3] = bb4.w;
        float* Xp = Xsm + s*65 + c4;
        Xp[0] = xx4.x; Xp[1] = xx4.y; Xp[2] = xx4.z; Xp[3] = xx4.w;
    }
    __syncthreads();

    int ty = tid >> 4, tx = tid & 15;

    // phase 1: G[t][s] = sum_n C[t][n] * B[s][n]
    float acc[4][4] = {};
    #pragma unroll 8
    for (int n = 0; n < 64; n++) {
        float a0 = Csm[(ty*4+0)*65 + n];
        float a1 = Csm[(ty*4+1)*65 + n];
        float a2 = Csm[(ty*4+2)*65 + n];
        float a3 = Csm[(ty*4+3)*65 + n];
        float b0 = Buf[(tx*4+0)*65 + n];
        float b1 = Buf[(tx*4+1)*65 + n];
        float b2 = Buf[(tx*4+2)*65 + n];
        float b3 = Buf[(tx*4+3)*65 + n];
        acc[0][0]=fmaf(a0,b0,acc[0][0]); acc[0][1]=fmaf(a0,b1,acc[0][1]);
        acc[0][2]=fmaf(a0,b2,acc[0][2]); acc[0][3]=fmaf(a0,b3,acc[0][3]);
        acc[1][0]=fmaf(a1,b0,acc[1][0]); acc[1][1]=fmaf(a1,b1,acc[1][1]);
        acc[1][2]=fmaf(a1,b2,acc[1][2]); acc[1][3]=fmaf(a1,b3,acc[1][3]);
        acc[2][0]=fmaf(a2,b0,acc[2][0]); acc[2][1]=fmaf(a2,b1,acc[2][1]);
        acc[2][2]=fmaf(a2,b2,acc[2][2]); acc[2][3]=fmaf(a2,b3,acc[2][3]);
        acc[3][0]=fmaf(a3,b0,acc[3][0]); acc[3][1]=fmaf(a3,b1,acc[3][1]);
        acc[3][2]=fmaf(a3,b2,acc[3][2]); acc[3][3]=fmaf(a3,b3,acc[3][3]);
    }
    __syncthreads();   // B reads done -> reuse Buf for masked G

    #pragma unroll
    for (int i = 0; i < 4; i++) {
        int t_ = ty*4 + i;
        #pragma unroll
        for (int j = 0; j < 4; j++) {
            int s_ = tx*4 + j;
            float m = (s_ <= t_) ? __expf(A * (csh[t_] - csh[s_])) * dsh[s_] : 0.f;
            Buf[t_*65 + s_] = acc[i][j] * m;
        }
    }
    __syncthreads();

    // phase 2: Y1[t][d] = sum_s Gm[t][s] * X[s][d]
    float y1[4][4] = {};
    #pragma unroll 8
    for (int s = 0; s < 64; s++) {
        float a0 = Buf[(ty*4+0)*65 + s];
        float a1 = Buf[(ty*4+1)*65 + s];
        float a2 = Buf[(ty*4+2)*65 + s];
        float a3 = Buf[(ty*4+3)*65 + s];
        float b0 = Xsm[s*65 + tx*4 + 0];
        float b1 = Xsm[s*65 + tx*4 + 1];
        float b2 = Xsm[s*65 + tx*4 + 2];
        float b3 = Xsm[s*65 + tx*4 + 3];
        y1[0][0]=fmaf(a0,b0,y1[0][0]); y1[0][1]=fmaf(a0,b1,y1[0][1]);
        y1[0][2]=fmaf(a0,b2,y1[0][2]); y1[0][3]=fmaf(a0,b3,y1[0][3]);
        y1[1][0]=fmaf(a1,b0,y1[1][0]); y1[1][1]=fmaf(a1,b1,y1[1][1]);
        y1[1][2]=fmaf(a1,b2,y1[1][2]); y1[1][3]=fmaf(a1,b3,y1[1][3]);
        y1[2][0]=fmaf(a2,b0,y1[2][0]); y1[2][1]=fmaf(a2,b1,y1[2][1]);
        y1[2][2]=fmaf(a2,b2,y1[2][2]); y1[2][3]=fmaf(a2,b3,y1[2][3]);
        y1[3][0]=fmaf(a3,b0,y1[3][0]); y1[3][1]=fmaf(a3,b1,y1[3][1]);
        y1[3][2]=fmaf(a3,b2,y1[3][2]); y1[3][3]=fmaf(a3,b3,y1[3][3]);
    }
    __syncthreads();   // Gm done -> reuse Buf for h_prev

    #pragma unroll
    for (int i = 0; i < 4; i++) {
        int n  = (tid >> 4) + i * 16;
        int c4 = (tid & 15) << 2;
        float4 hh = *(const float4*)(hp + (size_t)blk * 4096 + n*64 + c4);
        float* Hp = Buf + n*65 + c4;
        Hp[0] = hh.x; Hp[1] = hh.y; Hp[2] = hh.z; Hp[3] = hh.w;
    }
    __syncthreads();

    // phase 3: Y2[t][d] = sum_n C[t][n] * H[n][d]
    float y2[4][4] = {};
    #pragma unroll 8
    for (int n = 0; n < 64; n++) {
        float a0 = Csm[(ty*4+0)*65 + n];
        float a1 = Csm[(ty*4+1)*65 + n];
        float a2 = Csm[(ty*4+2)*65 + n];
        float a3 = Csm[(ty*4+3)*65 + n];
        float b0 = Buf[n*65 + tx*4 + 0];
        float b1 = Buf[n*65 + tx*4 + 1];
        float b2 = Buf[n*65 + tx*4 + 2];
        float b3 = Buf[n*65 + tx*4 + 3];
        y2[0][0]=fmaf(a0,b0,y2[0][0]); y2[0][1]=fmaf(a0,b1,y2[0][1]);
        y2[0][2]=fmaf(a0,b2,y2[0][2]); y2[0][3]=fmaf(a0,b3,y2[0][3]);
        y2[1][0]=fmaf(a1,b0,y2[1][0]); y2[1][1]=fmaf(a1,b1,y2[1][1]);
        y2[1][2]=fmaf(a1,b2,y2[1][2]); y2[1][3]=fmaf(a1,b3,y2[1][3]);
        y2[2][0]=fmaf(a2,b0,y2[2][0]); y2[2][1]=fmaf(a2,b1,y2[2][1]);
        y2[2][2]=fmaf(a2,b2,y2[2][2]); y2[2][3]=fmaf(a2,b3,y2[2][3]);
        y2[3][0]=fmaf(a3,b0,y2[3][0]); y2[3][1]=fmaf(a3,b1,y2[3][1]);
        y2[3][2]=fmaf(a3,b2,y2[3][2]); y2[3][3]=fmaf(a3,b3,y2[3][3]);
    }

    // epilogue: + D*x, gate with silu(z), write to combined gated buffer
    float d0 = Dv[h*64 + tx*4 + 0];
    float d1 = Dv[h*64 + tx*4 + 1];
    float d2 = Dv[h*64 + tx*4 + 2];
    float d3 = Dv[h*64 + tx*4 + 3];
    #pragma unroll
    for (int i = 0; i < 4; i++) {
        int t_ = ty*4 + i;
        int p = c * Q_ + t_;
        int l = dir ? (L_ - 1 - p) : p;
        float lam = __expf(A * csh[t_]);
        const float* row = proj + (size_t)(b * L_ + l) * PROJ_;
        float4 zz = *(const float4*)(row + h*64 + tx*4);
        float xr0 = Xsm[t_*65 + tx*4 + 0];
        float xr1 = Xsm[t_*65 + tx*4 + 1];
        float xr2 = Xsm[t_*65 + tx*4 + 2];
        float xr3 = Xsm[t_*65 + tx*4 + 3];
        float4 o;
        float yv;
        yv = y1[i][0] + lam * y2[i][0] + d0 * xr0;
        o.x = yv * (zz.x / (1.f + __expf(-zz.x)));
        yv = y1[i][1] + lam * y2[i][1] + d1 * xr1;
        o.y = yv * (zz.y / (1.f + __expf(-zz.y)));
        yv = y1[i][2] + lam * y2[i][2] + d2 * xr2;
        o.z = yv * (zz.z / (1.f + __expf(-zz.z)));
        yv = y1[i][3] + lam * y2[i][3] + d3 * xr3;
        o.w = yv * (zz.w / (1.f + __expf(-zz.w)));
        *(float4*)(gated + (size_t)(b * L_ + l) * DI2_ + dir*DI_ + h*64 + tx*4) = o;
    }
}

// ---------------- host launch ----------------
static float* sym(const void* s) {
    void* p = nullptr;
    cudaGetSymbolAddress(&p, s);
    return (float*)p;
}

extern "C" void kernel_launch(void* const* d_in, const int* in_sizes, int n_in,
                              void* d_out, int out_size) {
    const float* points = (const float*)d_in[0];
    const float* g1  = (const float*)d_in[1];
    const float* be1 = (const float*)d_in[2];
    const float* g2  = (const float*)d_in[3];
    const float* be2 = (const float*)d_in[4];
    const float* Winf  = (const float*)d_in[5];
    const float* binf  = (const float*)d_in[6];
    const float* dtbf  = (const float*)d_in[7];
    const float* Alogf = (const float*)d_in[8];
    const float* Df    = (const float*)d_in[9];
    const float* Woutf = (const float*)d_in[10];
    const float* boutf = (const float*)d_in[11];
    const float* Winb  = (const float*)d_in[12];
    const float* binb  = (const float*)d_in[13];
    const float* dtbb  = (const float*)d_in[14];
    const float* Alogb = (const float*)d_in[15];
    const float* Db    = (const float*)d_in[16];
    const float* Woutb = (const float*)d_in[17];
    const float* boutb = (const float*)d_in[18];
    const float* W1  = (const float*)d_in[19];
    const float* b1m = (const float*)d_in[20];
    const float* bng = (const float*)d_in[21];
    const float* bnb = (const float*)d_in[22];
    const float* W2  = (const float*)d_in[23];
    const float* b2m = (const float*)d_in[24];
    float* out = (float*)d_out;

    float* xln   = sym(g_xln);
    float* projf = sym(g_projf);
    float* projb = sym(g_projb);
    float* gated = sym(g_gated);
    float* x2    = sym(g_x2);
    float* h2    = sym(g_h2);
    float* hid   = sym(g_hid);
    float* wcat  = sym(g_wcat);
    float* bcat  = sym(g_bcat);
    float* ST    = sym(g_ST);
    float* hp    = sym(g_hp);
    float* dts   = sym(g_dts);
    float* css   = sym(g_css);
    float* dtsum = sym(g_dtsum);

    int smemC = (3 * 64 * 65 + 128) * sizeof(float);
    cudaFuncSetAttribute(chunk_out_kernel, cudaFuncAttributeMaxDynamicSharedMemorySize, smemC);

    // 1. LN1
    ln_kernel<<<M_, 128>>>(points, g1, be1, xln);

    // 1b. stack output-proj weights on K
    prep_wcat<<<(DI_ * C_ + 255) / 256, 256>>>(Woutf, Woutb, boutf, boutb, wcat, bcat);

    // 2/3. input projections
    dim3 gproj((PROJ_ + BN - 1) / BN, M_ / BM);
    gemm_kernel<false, 0><<<gproj, 256>>>(xln, Winf, binf, projf, M_, PROJ_, C_, nullptr, nullptr);
    gemm_kernel<false, 0><<<gproj, 256>>>(xln, Winb, binb, projb, M_, PROJ_, C_, nullptr, nullptr);

    // 4. chunked bidirectional scan
    chunk_state_kernel<<<NBLK_, 256>>>(projf, projb, dtbf, Alogf, dtbb, Alogb,
                                       ST, dts, css, dtsum);
    state_pass_kernel<<<2 * B_ * H_, 256>>>(ST, hp, dtsum, Alogf, Alogb);
    chunk_out_kernel<<<NBLK_, 256, smemC>>>(projf, projb, Alogf, Alogb, Df, Db,
                                            dts, css, hp, gated);

    // 5. fused output projection (K-concat) + residual -> x2
    dim3 gwout(C_ / BN, M_ / BM);
    gemm_kernel<false, 2><<<gwout, 256>>>(gated, wcat, bcat, x2, M_, C_, DI2_, points, nullptr);

    // 6. LN2
    ln_kernel<<<M_, 128>>>(x2, g2, be2, h2);

    // 7. MLP up
    dim3 gmlp1(HID_ / BN, M_ / BM);
    gemm_kernel<true, 1><<<gmlp1, 256>>>(h2, W1, b1m, hid, M_, HID_, C_, bng, bnb);

    // 8. MLP down + residual -> d_out
    dim3 gmlp2(C_ / BN, M_ / BM);
    gemm_kernel<true, 2><<<gmlp2, 256>>>(hid, W2, b2m, out, M_, C_, HID_, x2, nullptr);
}

// round 6
// speedup vs baseline: 3.1015x; 1.6485x over previous
#include <cuda_runtime.h>
#include <cuda_bf16.h>
#include <math.h>
#include <stdint.h>

// ---------------- problem constants ----------------
#define B_   4
#define L_   2048
#define C_   384
#define H_   12
#define N_   64
#define DI_  768
#define DI2_ 1536
#define HID_ 1536
#define PROJ_ 1676          // 2*DI + 2*N + H
#define M_   (B_*L_)        // 8192
#define EPS_ 1e-5f

#define Q_    64            // chunk length
#define NC_   32            // chunks per sequence (L/Q)
#define NBLK_ (2*B_*H_*NC_) // 3072

// ---------------- scratch (no allocations allowed) ----------------
__device__ float g_xln  [M_*C_];
__device__ float g_projf[M_*PROJ_];
__device__ float g_projb[M_*PROJ_];
__device__ float g_gated[M_*DI2_];     // [fwd(768) | bwd(768)] per row
__device__ float g_x2   [M_*C_];
__device__ float g_h2   [M_*C_];
__device__ float g_hid  [M_*HID_];
__device__ float g_wcat [DI2_*C_];     // [Woutf ; Woutb] stacked on K
__device__ float g_bcat [C_];
__device__ float g_ST   [(size_t)NBLK_*64*64];
__device__ float g_hp   [(size_t)NBLK_*64*64];
__device__ float g_dts  [NBLK_*Q_];
__device__ float g_css  [NBLK_*Q_];
__device__ float g_dtsum[NBLK_];

// ---------------- block reduction (128 threads) ----------------
__device__ __forceinline__ float blockSum128(float v) {
    __shared__ float sh[4];
    int lane = threadIdx.x & 31, w = threadIdx.x >> 5;
    #pragma unroll
    for (int o = 16; o; o >>= 1) v += __shfl_xor_sync(0xffffffffu, v, o);
    if (lane == 0) sh[w] = v;
    __syncthreads();
    float r = sh[0] + sh[1] + sh[2] + sh[3];
    __syncthreads();
    return r;
}

// ---------------- LayerNorm (row of 384) ----------------
__global__ void ln_kernel(const float* __restrict__ x,
                          const float* __restrict__ g,
                          const float* __restrict__ be,
                          float* __restrict__ o) {
    size_t row = blockIdx.x;
    const float* xr = x + row * C_;
    int t = threadIdx.x;
    float v0 = xr[t], v1 = xr[t + 128], v2 = xr[t + 256];
    float mu = blockSum128(v0 + v1 + v2) * (1.f / C_);
    float d0 = v0 - mu, d1 = v1 - mu, d2 = v2 - mu;
    float var = blockSum128(d0*d0 + d1*d1 + d2*d2) * (1.f / C_);
    float inv = rsqrtf(var + EPS_);
    float* orow = o + row * C_;
    orow[t]       = d0 * inv * g[t]       + be[t];
    orow[t + 128] = d1 * inv * g[t + 128] + be[t + 128];
    orow[t + 256] = d2 * inv * g[t + 256] + be[t + 256];
}

// ---------------- weight concat for fused output projection ----------------
__global__ void prep_wcat(const float* __restrict__ Wf, const float* __restrict__ Wb,
                          const float* __restrict__ bf, const float* __restrict__ bb,
                          float* __restrict__ Wcat, float* __restrict__ bcat) {
    int i = blockIdx.x * 256 + threadIdx.x;
    if (i < DI_ * C_) {
        Wcat[i] = Wf[i];
        Wcat[DI_ * C_ + i] = Wb[i];
    }
    if (i < C_) bcat[i] = bf[i] + bb[i];
}

// ---------------- TF32 helpers ----------------
__device__ __forceinline__ uint32_t f2tf(float f) {
    uint32_t u;
    asm("cvt.rna.tf32.f32 %0, %1;" : "=r"(u) : "f"(f));
    return u;
}
__device__ __forceinline__ void mma_tf32(float& d0, float& d1, float& d2, float& d3,
                                         uint32_t a0, uint32_t a1, uint32_t a2, uint32_t a3,
                                         uint32_t b0, uint32_t b1) {
    asm volatile("mma.sync.aligned.m16n8k8.row.col.f32.tf32.tf32.f32 "
                 "{%0,%1,%2,%3}, {%4,%5,%6,%7}, {%8,%9}, {%0,%1,%2,%3};\n"
                 : "+f"(d0), "+f"(d1), "+f"(d2), "+f"(d3)
                 : "r"(a0), "r"(a1), "r"(a2), "r"(a3), "r"(b0), "r"(b1));
}

// ---------------- TF32 tensor-core GEMM: 128x128x16, double buffered ----------
// C[M,N] = A[M,K] @ B + bias (+ epilogue)
// BT=false: B is (K,N) row-major.  BT=true: B is (N,K) row-major (A@B^T).
// EPI: 0 = +bias; 1 = +bias,*bn_scale,+bn_bias,relu; 2 = +bias + residual(e1)
#define BM 128
#define BN 128
#define BK 16

template<bool BT, int EPI>
__global__ __launch_bounds__(256, 2)
void gemm_kernel(const float* __restrict__ A, const float* __restrict__ Bm,
                 const float* __restrict__ bias, float* __restrict__ C,
                 int M, int N, int K,
                 const float* __restrict__ e1, const float* __restrict__ e2) {
    __shared__ uint32_t As[2][BK][BM + 4];
    __shared__ uint32_t Bs[2][BK][BN + 4];
    int tid = threadIdx.x;
    int gm0 = blockIdx.y * BM, gn0 = blockIdx.x * BN;

    // loader indices
    int ar = tid >> 2;              // 0..63
    int ac = (tid & 3) << 2;        // 0,4,8,12
    int bkr = tid >> 4;             // 0..15 (NN path)
    int bnc = (tid & 15) << 2;      // 0..60

    // mma indices
    int lane = tid & 31, wid = tid >> 5;
    int wm = (wid >> 2) << 6;       // 0 / 64
    int wn = (wid & 3) << 5;        // 0,32,64,96
    int g = lane >> 2, tg = lane & 3;

    float4 a0, a1, b0, b1;
    const float4 z4 = {0.f, 0.f, 0.f, 0.f};

    // ---- prologue: load k-tile 0 ----
    {
        const float* Ap = A + (size_t)(gm0 + ar) * K + ac;
        a0 = *(const float4*)(Ap);
        a1 = *(const float4*)(Ap + (size_t)64 * K);
        if (BT) {
            const float* Bp = Bm + (size_t)(gn0 + ar) * K + ac;
            b0 = *(const float4*)(Bp);
            b1 = *(const float4*)(Bp + (size_t)64 * K);
        } else {
            int n0 = gn0 + bnc;
            const float* Bp = Bm + (size_t)bkr * N;
            b0 = (n0 < N) ? *(const float4*)(Bp + n0) : z4;
            b1 = (n0 + 64 < N) ? *(const float4*)(Bp + n0 + 64) : z4;
        }
    }
    As[0][ac+0][ar] = f2tf(a0.x); As[0][ac+1][ar] = f2tf(a0.y);
    As[0][ac+2][ar] = f2tf(a0.z); As[0][ac+3][ar] = f2tf(a0.w);
    As[0][ac+0][ar+64] = f2tf(a1.x); As[0][ac+1][ar+64] = f2tf(a1.y);
    As[0][ac+2][ar+64] = f2tf(a1.z); As[0][ac+3][ar+64] = f2tf(a1.w);
    if (BT) {
        Bs[0][ac+0][ar] = f2tf(b0.x); Bs[0][ac+1][ar] = f2tf(b0.y);
        Bs[0][ac+2][ar] = f2tf(b0.z); Bs[0][ac+3][ar] = f2tf(b0.w);
        Bs[0][ac+0][ar+64] = f2tf(b1.x); Bs[0][ac+1][ar+64] = f2tf(b1.y);
        Bs[0][ac+2][ar+64] = f2tf(b1.z); Bs[0][ac+3][ar+64] = f2tf(b1.w);
    } else {
        Bs[0][bkr][bnc+0] = f2tf(b0.x); Bs[0][bkr][bnc+1] = f2tf(b0.y);
        Bs[0][bkr][bnc+2] = f2tf(b0.z); Bs[0][bkr][bnc+3] = f2tf(b0.w);
        Bs[0][bkr][bnc+64] = f2tf(b1.x); Bs[0][bkr][bnc+65] = f2tf(b1.y);
        Bs[0][bkr][bnc+66] = f2tf(b1.z); Bs[0][bkr][bnc+67] = f2tf(b1.w);
    }
    __syncthreads();

    float acc[4][4][4];
    #pragma unroll
    for (int i = 0; i < 4; i++)
        #pragma unroll
        for (int j = 0; j < 4; j++)
            #pragma unroll
            for (int r = 0; r < 4; r++) acc[i][j][r] = 0.f;

    int nkt = K / BK;
    int buf = 0;
    for (int kt = 0; kt < nkt; ++kt) {
        // prefetch next k-tile into registers
        if (kt + 1 < nkt) {
            int gk = (kt + 1) * BK;
            const float* Ap = A + (size_t)(gm0 + ar) * K + gk + ac;
            a0 = *(const float4*)(Ap);
            a1 = *(const float4*)(Ap + (size_t)64 * K);
            if (BT) {
                const float* Bp = Bm + (size_t)(gn0 + ar) * K + gk + ac;
                b0 = *(const float4*)(Bp);
                b1 = *(const float4*)(Bp + (size_t)64 * K);
            } else {
                int n0 = gn0 + bnc;
                const float* Bp = Bm + (size_t)(gk + bkr) * N;
                b0 = (n0 < N) ? *(const float4*)(Bp + n0) : z4;
                b1 = (n0 + 64 < N) ? *(const float4*)(Bp + n0 + 64) : z4;
            }
        }
        // compute on current buffer: 2 k8-steps
        #pragma unroll
        for (int ks = 0; ks < 2; ks++) {
            int kk = ks * 8;
            uint32_t af[4][4];
            #pragma unroll
            for (int i = 0; i < 4; i++) {
                int m = wm + i * 16 + g;
                af[i][0] = As[buf][kk + tg][m];
                af[i][1] = As[buf][kk + tg][m + 8];
                af[i][2] = As[buf][kk + tg + 4][m];
                af[i][3] = As[buf][kk + tg + 4][m + 8];
            }
            uint32_t bfr[4][2];
            #pragma unroll
            for (int j = 0; j < 4; j++) {
                int n = wn + j * 8 + g;
                bfr[j][0] = Bs[buf][kk + tg][n];
                bfr[j][1] = Bs[buf][kk + tg + 4][n];
            }
            #pragma unroll
            for (int i = 0; i < 4; i++)
                #pragma unroll
                for (int j = 0; j < 4; j++)
                    mma_tf32(acc[i][j][0], acc[i][j][1], acc[i][j][2], acc[i][j][3],
                             af[i][0], af[i][1], af[i][2], af[i][3],
                             bfr[j][0], bfr[j][1]);
        }
        // stage next tile into other buffer
        if (kt + 1 < nkt) {
            int nb2 = buf ^ 1;
            As[nb2][ac+0][ar] = f2tf(a0.x); As[nb2][ac+1][ar] = f2tf(a0.y);
            As[nb2][ac+2][ar] = f2tf(a0.z); As[nb2][ac+3][ar] = f2tf(a0.w);
            As[nb2][ac+0][ar+64] = f2tf(a1.x); As[nb2][ac+1][ar+64] = f2tf(a1.y);
            As[nb2][ac+2][ar+64] = f2tf(a1.z); As[nb2][ac+3][ar+64] = f2tf(a1.w);
            if (BT) {
                Bs[nb2][ac+0][ar] = f2tf(b0.x); Bs[nb2][ac+1][ar] = f2tf(b0.y);
                Bs[nb2][ac+2][ar] = f2tf(b0.z); Bs[nb2][ac+3][ar] = f2tf(b0.w);
                Bs[nb2][ac+0][ar+64] = f2tf(b1.x); Bs[nb2][ac+1][ar+64] = f2tf(b1.y);
                Bs[nb2][ac+2][ar+64] = f2tf(b1.z); Bs[nb2][ac+3][ar+64] = f2tf(b1.w);
            } else {
                Bs[nb2][bkr][bnc+0] = f2tf(b0.x); Bs[nb2][bkr][bnc+1] = f2tf(b0.y);
                Bs[nb2][bkr][bnc+2] = f2tf(b0.z); Bs[nb2][bkr][bnc+3] = f2tf(b0.w);
                Bs[nb2][bkr][bnc+64] = f2tf(b1.x); Bs[nb2][bkr][bnc+65] = f2tf(b1.y);
                Bs[nb2][bkr][bnc+66] = f2tf(b1.z); Bs[nb2][bkr][bnc+67] = f2tf(b1.w);
            }
            __syncthreads();
            buf ^= 1;
        }
    }

    // ---- epilogue ----
    const float bnrs = rsqrtf(1.f + EPS_);
    #pragma unroll
    for (int i = 0; i < 4; i++) {
        #pragma unroll
        for (int rh = 0; rh < 2; rh++) {
            int m = gm0 + wm + i * 16 + g + rh * 8;
            #pragma unroll
            for (int j = 0; j < 4; j++) {
                int n = gn0 + wn + j * 8 + 2 * tg;
                if (n < N) {
                    float v0 = acc[i][j][rh * 2 + 0] + bias[n];
                    float v1 = acc[i][j][rh * 2 + 1] + bias[n + 1];
                    if (EPI == 1) {
                        v0 = fmaxf(v0 * (e1[n] * bnrs) + e2[n], 0.f);
                        v1 = fmaxf(v1 * (e1[n + 1] * bnrs) + e2[n + 1], 0.f);
                    } else if (EPI == 2) {
                        const float* rp = e1 + (size_t)m * N + n;
                        v0 += rp[0]; v1 += rp[1];
                    }
                    float2 o2 = {v0, v1};
                    *(float2*)(C + (size_t)m * N + n) = o2;
                }
            }
        }
    }
}

// ============ chunked selective scan (unchanged from R5) ============
__global__ __launch_bounds__(256)
void chunk_state_kernel(const float* __restrict__ projf, const float* __restrict__ projb,
                        const float* __restrict__ dtbf, const float* __restrict__ Alogf,
                        const float* __restrict__ dtbb, const float* __restrict__ Alogb,
                        float* __restrict__ ST, float* __restrict__ dts,
                        float* __restrict__ css, float* __restrict__ dtsum) {
    int blk = blockIdx.x;
    int c   = blk & (NC_ - 1);
    int h   = (blk >> 5) % H_;
    int b   = (blk / (NC_ * H_)) & (B_ - 1);
    int dir = blk / (NC_ * H_ * B_);
    const float* proj = dir ? projb : projf;
    float A    = -expf((dir ? Alogb : Alogf)[h]);
    float dtbh = (dir ? dtbb : dtbf)[h];

    __shared__ float Bsm[Q_ * 65];
    __shared__ float Xw [Q_ * 65];
    __shared__ float dsh[Q_], csh[Q_];

    int tid = threadIdx.x;
    if (tid < Q_) {
        int p = c * Q_ + tid;
        int l = dir ? (L_ - 1 - p) : p;
        float raw = proj[(size_t)(b * L_ + l) * PROJ_ + 2*DI_ + 2*N_ + h] + dtbh;
        float dt = (raw > 20.f) ? raw : log1pf(__expf(raw));
        dsh[tid] = dt;
        csh[tid] = dt;
    }
    __syncthreads();
    for (int off = 1; off < Q_; off <<= 1) {
        float v = 0.f;
        if (tid < Q_ && tid >= off) v = csh[tid - off];
        __syncthreads();
        if (tid < Q_ && tid >= off) csh[tid] += v;
        __syncthreads();
    }
    float cend = csh[Q_ - 1];
    if (tid < Q_) {
        dts[blk * Q_ + tid] = dsh[tid];
        css[blk * Q_ + tid] = csh[tid];
    }
    if (tid == 0) dtsum[blk] = cend;

    #pragma unroll
    for (int i = 0; i < 4; i++) {
        int s  = (tid >> 4) + i * 16;
        int c4 = (tid & 15) << 2;
        int p = c * Q_ + s;
        int l = dir ? (L_ - 1 - p) : p;
        const float* row = proj + (size_t)(b * L_ + l) * PROJ_;
        float4 bb = *(const float4*)(row + 2*DI_ + c4);
        float4 xx = *(const float4*)(row + DI_ + h*64 + c4);
        float w = __expf(A * (cend - csh[s])) * dsh[s];
        float* Bp = Bsm + s * 65 + c4;
        Bp[0] = bb.x; Bp[1] = bb.y; Bp[2] = bb.z; Bp[3] = bb.w;
        float* Xp = Xw + s * 65 + c4;
        Xp[0] = w * xx.x; Xp[1] = w * xx.y; Xp[2] = w * xx.z; Xp[3] = w * xx.w;
    }
    __syncthreads();

    int ty = tid >> 4, tx = tid & 15;
    float acc[4][4] = {};
    #pragma unroll 8
    for (int s = 0; s < Q_; s++) {
        float a0 = Bsm[s*65 + ty*4 + 0];
        float a1 = Bsm[s*65 + ty*4 + 1];
        float a2 = Bsm[s*65 + ty*4 + 2];
        float a3 = Bsm[s*65 + ty*4 + 3];
        float b0 = Xw[s*65 + tx*4 + 0];
        float b1 = Xw[s*65 + tx*4 + 1];
        float b2 = Xw[s*65 + tx*4 + 2];
        float b3 = Xw[s*65 + tx*4 + 3];
        acc[0][0] = fmaf(a0,b0,acc[0][0]); acc[0][1] = fmaf(a0,b1,acc[0][1]);
        acc[0][2] = fmaf(a0,b2,acc[0][2]); acc[0][3] = fmaf(a0,b3,acc[0][3]);
        acc[1][0] = fmaf(a1,b0,acc[1][0]); acc[1][1] = fmaf(a1,b1,acc[1][1]);
        acc[1][2] = fmaf(a1,b2,acc[1][2]); acc[1][3] = fmaf(a1,b3,acc[1][3]);
        acc[2][0] = fmaf(a2,b0,acc[2][0]); acc[2][1] = fmaf(a2,b1,acc[2][1]);
        acc[2][2] = fmaf(a2,b2,acc[2][2]); acc[2][3] = fmaf(a2,b3,acc[2][3]);
        acc[3][0] = fmaf(a3,b0,acc[3][0]); acc[3][1] = fmaf(a3,b1,acc[3][1]);
        acc[3][2] = fmaf(a3,b2,acc[3][2]); acc[3][3] = fmaf(a3,b3,acc[3][3]);
    }
    #pragma unroll
    for (int i = 0; i < 4; i++) {
        float4 v = {acc[i][0], acc[i][1], acc[i][2], acc[i][3]};
        *(float4*)(ST + (size_t)blk * 4096 + (ty*4 + i) * 64 + tx*4) = v;
    }
}

__global__ __launch_bounds__(256)
void state_pass_kernel(const float* __restrict__ ST, float* __restrict__ hp,
                       const float* __restrict__ dtsum,
                       const float* __restrict__ Alogf, const float* __restrict__ Alogb) {
    int g = blockIdx.x;
    int dir = g / (B_ * H_);
    int h = g % H_;
    float A = -expf((dir ? Alogb : Alogf)[h]);
    int t = threadIdx.x;
    float hreg[16];
    #pragma unroll
    for (int k = 0; k < 16; k++) hreg[k] = 0.f;
    size_t base = (size_t)g * NC_ * 4096;
    for (int cc = 0; cc < NC_; cc++) {
        size_t o = base + (size_t)cc * 4096 + t;
        float al = expf(A * dtsum[g * NC_ + cc]);
        float sv[16];
        #pragma unroll
        for (int k = 0; k < 16; k++) sv[k] = ST[o + k*256];
        #pragma unroll
        for (int k = 0; k < 16; k++) {
            hp[o + k*256] = hreg[k];
            hreg[k] = al * hreg[k] + sv[k];
        }
    }
}

extern __shared__ float smc[];
__global__ __launch_bounds__(256)
void chunk_out_kernel(const float* __restrict__ projf, const float* __restrict__ projb,
                      const float* __restrict__ Alogf, const float* __restrict__ Alogb,
                      const float* __restrict__ Df, const float* __restrict__ Db,
                      const float* __restrict__ dts, const float* __restrict__ css,
                      const float* __restrict__ hp, float* __restrict__ gated) {
    int blk = blockIdx.x;
    int c   = blk & (NC_ - 1);
    int h   = (blk >> 5) % H_;
    int b   = (blk / (NC_ * H_)) & (B_ - 1);
    int dir = blk / (NC_ * H_ * B_);
    const float* proj = dir ? projb : projf;
    const float* Dv   = dir ? Db : Df;
    float A = -expf((dir ? Alogb : Alogf)[h]);

    float* Csm = smc;
    float* Buf = smc + 64*65;
    float* Xsm = smc + 2*64*65;
    float* dsh = smc + 3*64*65;
    float* csh = dsh + 64;

    int tid = threadIdx.x;
    if (tid < Q_) {
        dsh[tid] = dts[blk * Q_ + tid];
        csh[tid] = css[blk * Q_ + tid];
    }
    #pragma unroll
    for (int i = 0; i < 4; i++) {
        int s  = (tid >> 4) + i * 16;
        int c4 = (tid & 15) << 2;
        int p = c * Q_ + s;
        int l = dir ? (L_ - 1 - p) : p;
        const float* row = proj + (size_t)(b * L_ + l) * PROJ_;
        float4 cc4 = *(const float4*)(row + 2*DI_ + N_ + c4);
        float4 bb4 = *(const float4*)(row + 2*DI_ + c4);
        float4 xx4 = *(const float4*)(row + DI_ + h*64 + c4);
        float* Cp = Csm + s*65 + c4;
        Cp[0] = cc4.x; Cp[1] = cc4.y; Cp[2] = cc4.z; Cp[3] = cc4.w;
        float* Bp = Buf + s*65 + c4;
        Bp[0] = bb4.x; Bp[1] = bb4.y; Bp[2] = bb4.z; Bp[3] = bb4.w;
        float* Xp = Xsm + s*65 + c4;
        Xp[0] = xx4.x; Xp[1] = xx4.y; Xp[2] = xx4.z; Xp[3] = xx4.w;
    }
    __syncthreads();

    int ty = tid >> 4, tx = tid & 15;

    float acc[4][4] = {};
    #pragma unroll 8
    for (int n = 0; n < 64; n++) {
        float a0 = Csm[(ty*4+0)*65 + n];
        float a1 = Csm[(ty*4+1)*65 + n];
        float a2 = Csm[(ty*4+2)*65 + n];
        float a3 = Csm[(ty*4+3)*65 + n];
        float b0 = Buf[(tx*4+0)*65 + n];
        float b1 = Buf[(tx*4+1)*65 + n];
        float b2 = Buf[(tx*4+2)*65 + n];
        float b3 = Buf[(tx*4+3)*65 + n];
        acc[0][0]=fmaf(a0,b0,acc[0][0]); acc[0][1]=fmaf(a0,b1,acc[0][1]);
        acc[0][2]=fmaf(a0,b2,acc[0][2]); acc[0][3]=fmaf(a0,b3,acc[0][3]);
        acc[1][0]=fmaf(a1,b0,acc[1][0]); acc[1][1]=fmaf(a1,b1,acc[1][1]);
        acc[1][2]=fmaf(a1,b2,acc[1][2]); acc[1][3]=fmaf(a1,b3,acc[1][3]);
        acc[2][0]=fmaf(a2,b0,acc[2][0]); acc[2][1]=fmaf(a2,b1,acc[2][1]);
        acc[2][2]=fmaf(a2,b2,acc[2][2]); acc[2][3]=fmaf(a2,b3,acc[2][3]);
        acc[3][0]=fmaf(a3,b0,acc[3][0]); acc[3][1]=fmaf(a3,b1,acc[3][1]);
        acc[3][2]=fmaf(a3,b2,acc[3][2]); acc[3][3]=fmaf(a3,b3,acc[3][3]);
    }
    __syncthreads();

    #pragma unroll
    for (int i = 0; i < 4; i++) {
        int t_ = ty*4 + i;
        #pragma unroll
        for (int j = 0; j < 4; j++) {
            int s_ = tx*4 + j;
            float m = (s_ <= t_) ? __expf(A * (csh[t_] - csh[s_])) * dsh[s_] : 0.f;
            Buf[t_*65 + s_] = acc[i][j] * m;
        }
    }
    __syncthreads();

    float y1[4][4] = {};
    #pragma unroll 8
    for (int s = 0; s < 64; s++) {
        float a0 = Buf[(ty*4+0)*65 + s];
        float a1 = Buf[(ty*4+1)*65 + s];
        float a2 = Buf[(ty*4+2)*65 + s];
        float a3 = Buf[(ty*4+3)*65 + s];
        float b0 = Xsm[s*65 + tx*4 + 0];
        float b1 = Xsm[s*65 + tx*4 + 1];
        float b2 = Xsm[s*65 + tx*4 + 2];
        float b3 = Xsm[s*65 + tx*4 + 3];
        y1[0][0]=fmaf(a0,b0,y1[0][0]); y1[0][1]=fmaf(a0,b1,y1[0][1]);
        y1[0][2]=fmaf(a0,b2,y1[0][2]); y1[0][3]=fmaf(a0,b3,y1[0][3]);
        y1[1][0]=fmaf(a1,b0,y1[1][0]); y1[1][1]=fmaf(a1,b1,y1[1][1]);
        y1[1][2]=fmaf(a1,b2,y1[1][2]); y1[1][3]=fmaf(a1,b3,y1[1][3]);
        y1[2][0]=fmaf(a2,b0,y1[2][0]); y1[2][1]=fmaf(a2,b1,y1[2][1]);
        y1[2][2]=fmaf(a2,b2,y1[2][2]); y1[2][3]=fmaf(a2,b3,y1[2][3]);
        y1[3][0]=fmaf(a3,b0,y1[3][0]); y1[3][1]=fmaf(a3,b1,y1[3][1]);
        y1[3][2]=fmaf(a3,b2,y1[3][2]); y1[3][3]=fmaf(a3,b3,y1[3][3]);
    }
    __syncthreads();

    #pragma unroll
    for (int i = 0; i < 4; i++) {
        int n  = (tid >> 4) + i * 16;
        int c4 = (tid & 15) << 2;
        float4 hh = *(const float4*)(hp + (size_t)blk * 4096 + n*64 + c4);
        float* Hp = Buf + n*65 + c4;
        Hp[0] = hh.x; Hp[1] = hh.y; Hp[2] = hh.z; Hp[3] = hh.w;
    }
    __syncthreads();

    float y2[4][4] = {};
    #pragma unroll 8
    for (int n = 0; n < 64; n++) {
        float a0 = Csm[(ty*4+0)*65 + n];
        float a1 = Csm[(ty*4+1)*65 + n];
        float a2 = Csm[(ty*4+2)*65 + n];
        float a3 = Csm[(ty*4+3)*65 + n];
        float b0 = Buf[n*65 + tx*4 + 0];
        float b1 = Buf[n*65 + tx*4 + 1];
        float b2 = Buf[n*65 + tx*4 + 2];
        float b3 = Buf[n*65 + tx*4 + 3];
        y2[0][0]=fmaf(a0,b0,y2[0][0]); y2[0][1]=fmaf(a0,b1,y2[0][1]);
        y2[0][2]=fmaf(a0,b2,y2[0][2]); y2[0][3]=fmaf(a0,b3,y2[0][3]);
        y2[1][0]=fmaf(a1,b0,y2[1][0]); y2[1][1]=fmaf(a1,b1,y2[1][1]);
        y2[1][2]=fmaf(a1,b2,y2[1][2]); y2[1][3]=fmaf(a1,b3,y2[1][3]);
        y2[2][0]=fmaf(a2,b0,y2[2][0]); y2[2][1]=fmaf(a2,b1,y2[2][1]);
        y2[2][2]=fmaf(a2,b2,y2[2][2]); y2[2][3]=fmaf(a2,b3,y2[2][3]);
        y2[3][0]=fmaf(a3,b0,y2[3][0]); y2[3][1]=fmaf(a3,b1,y2[3][1]);
        y2[3][2]=fmaf(a3,b2,y2[3][2]); y2[3][3]=fmaf(a3,b3,y2[3][3]);
    }

    float d0 = Dv[h*64 + tx*4 + 0];
    float d1 = Dv[h*64 + tx*4 + 1];
    float d2 = Dv[h*64 + tx*4 + 2];
    float d3 = Dv[h*64 + tx*4 + 3];
    #pragma unroll
    for (int i = 0; i < 4; i++) {
        int t_ = ty*4 + i;
        int p = c * Q_ + t_;
        int l = dir ? (L_ - 1 - p) : p;
        float lam = __expf(A * csh[t_]);
        const float* row = proj + (size_t)(b * L_ + l) * PROJ_;
        float4 zz = *(const float4*)(row + h*64 + tx*4);
        float xr0 = Xsm[t_*65 + tx*4 + 0];
        float xr1 = Xsm[t_*65 + tx*4 + 1];
        float xr2 = Xsm[t_*65 + tx*4 + 2];
        float xr3 = Xsm[t_*65 + tx*4 + 3];
        float4 o;
        float yv;
        yv = y1[i][0] + lam * y2[i][0] + d0 * xr0;
        o.x = yv * (zz.x / (1.f + __expf(-zz.x)));
        yv = y1[i][1] + lam * y2[i][1] + d1 * xr1;
        o.y = yv * (zz.y / (1.f + __expf(-zz.y)));
        yv = y1[i][2] + lam * y2[i][2] + d2 * xr2;
        o.z = yv * (zz.z / (1.f + __expf(-zz.z)));
        yv = y1[i][3] + lam * y2[i][3] + d3 * xr3;
        o.w = yv * (zz.w / (1.f + __expf(-zz.w)));
        *(float4*)(gated + (size_t)(b * L_ + l) * DI2_ + dir*DI_ + h*64 + tx*4) = o;
    }
}

// ---------------- host launch ----------------
static float* sym(const void* s) {
    void* p = nullptr;
    cudaGetSymbolAddress(&p, s);
    return (float*)p;
}

extern "C" void kernel_launch(void* const* d_in, const int* in_sizes, int n_in,
                              void* d_out, int out_size) {
    const float* points = (const float*)d_in[0];
    const float* g1  = (const float*)d_in[1];
    const float* be1 = (const float*)d_in[2];
    const float* g2  = (const float*)d_in[3];
    const float* be2 = (const float*)d_in[4];
    const float* Winf  = (const float*)d_in[5];
    const float* binf  = (const float*)d_in[6];
    const float* dtbf  = (const float*)d_in[7];
    const float* Alogf = (const float*)d_in[8];
    const float* Df    = (const float*)d_in[9];
    const float* Woutf = (const float*)d_in[10];
    const float* boutf = (const float*)d_in[11];
    const float* Winb  = (const float*)d_in[12];
    const float* binb  = (const float*)d_in[13];
    const float* dtbb  = (const float*)d_in[14];
    const float* Alogb = (const float*)d_in[15];
    const float* Db    = (const float*)d_in[16];
    const float* Woutb = (const float*)d_in[17];
    const float* boutb = (const float*)d_in[18];
    const float* W1  = (const float*)d_in[19];
    const float* b1m = (const float*)d_in[20];
    const float* bng = (const float*)d_in[21];
    const float* bnb = (const float*)d_in[22];
    const float* W2  = (const float*)d_in[23];
    const float* b2m = (const float*)d_in[24];
    float* out = (float*)d_out;

    float* xln   = sym(g_xln);
    float* projf = sym(g_projf);
    float* projb = sym(g_projb);
    float* gated = sym(g_gated);
    float* x2    = sym(g_x2);
    float* h2    = sym(g_h2);
    float* hid   = sym(g_hid);
    float* wcat  = sym(g_wcat);
    float* bcat  = sym(g_bcat);
    float* ST    = sym(g_ST);
    float* hp    = sym(g_hp);
    float* dts   = sym(g_dts);
    float* css   = sym(g_css);
    float* dtsum = sym(g_dtsum);

    int smemC = (3 * 64 * 65 + 128) * sizeof(float);
    cudaFuncSetAttribute(chunk_out_kernel, cudaFuncAttributeMaxDynamicSharedMemorySize, smemC);

    // 1. LN1
    ln_kernel<<<M_, 128>>>(points, g1, be1, xln);

    // 1b. stack output-proj weights on K
    prep_wcat<<<(DI_ * C_ + 255) / 256, 256>>>(Woutf, Woutb, boutf, boutb, wcat, bcat);

    // 2/3. input projections
    dim3 gproj((PROJ_ + BN - 1) / BN, M_ / BM);
    gemm_kernel<false, 0><<<gproj, 256>>>(xln, Winf, binf, projf, M_, PROJ_, C_, nullptr, nullptr);
    gemm_kernel<false, 0><<<gproj, 256>>>(xln, Winb, binb, projb, M_, PROJ_, C_, nullptr, nullptr);

    // 4. chunked bidirectional scan
    chunk_state_kernel<<<NBLK_, 256>>>(projf, projb, dtbf, Alogf, dtbb, Alogb,
                                       ST, dts, css, dtsum);
    state_pass_kernel<<<2 * B_ * H_, 256>>>(ST, hp, dtsum, Alogf, Alogb);
    chunk_out_kernel<<<NBLK_, 256, smemC>>>(projf, projb, Alogf, Alogb, Df, Db,
                                            dts, css, hp, gated);

    // 5. fused output projection (K-concat) + residual -> x2
    dim3 gwout(C_ / BN, M_ / BM);
    gemm_kernel<false, 2><<<gwout, 256>>>(gated, wcat, bcat, x2, M_, C_, DI2_, points, nullptr);

    // 6. LN2
    ln_kernel<<<M_, 128>>>(x2, g2, be2, h2);

    // 7. MLP up
    dim3 gmlp1(HID_ / BN, M_ / BM);
    gemm_kernel<true, 1><<<gmlp1, 256>>>(h2, W1, b1m, hid, M_, HID_, C_, bng, bnb);

    // 8. MLP down + residual -> d_out
    dim3 gmlp2(C_ / BN, M_ / BM);
    gemm_kernel<true, 2><<<gmlp2, 256>>>(hid, W2, b2m, out, M_, C_, HID_, x2, nullptr);
}